// round 1
// baseline (speedup 1.0000x reference)
#include <cuda_runtime.h>
#include <cstdint>

#define H 128
#define APAD 132          // padded row stride (floats) for smem A tiles
#define ROWS 64           // rows per block tile
#define MAX_E 250000
#define MAX_T 1000000

// Scratch (allowed: __device__ globals, no runtime allocation)
__device__ float g_edge_down[(size_t)MAX_E * H];   // 128 MB
__device__ float g_m[(size_t)MAX_E * H];           // 128 MB

__device__ __forceinline__ float silu(float v) {
    return v / (1.0f + __expf(-v));
}

// ---------------------------------------------------------------------------
// Register-tiled GEMM: block computes a [64 x 128] output tile.
// A tile resident in smem As[64][APAD] (row-major). W [kreal x 128] row-major
// in global, streamed through Ws[16][128] in smem. 256 threads = 16x16 grid,
// each thread accumulates a 4(row) x 8(col) micro-tile.
// Starts with __syncthreads() so callers may fill As right before the call.
// ---------------------------------------------------------------------------
template <int KD>
__device__ __forceinline__ void gemm_tile(const float* __restrict__ As,
                                          float* __restrict__ Ws,
                                          const float* __restrict__ W,
                                          int kreal, int trow, int tcol,
                                          float acc[4][8]) {
    const int tid = threadIdx.x;
#pragma unroll
    for (int kk = 0; kk < KD; kk += 16) {
        __syncthreads();
#pragma unroll
        for (int i = 0; i < 8; ++i) {
            int idx = i * 256 + tid;           // 0..2047 -> Ws[16][128]
            int kr = kk + (idx >> 7);
            Ws[idx] = (kr < kreal) ? __ldg(&W[(size_t)kr * H + (idx & 127)]) : 0.0f;
        }
        __syncthreads();
#pragma unroll
        for (int k2 = 0; k2 < 16; k2 += 4) {
            float4 a[4];
#pragma unroll
            for (int i = 0; i < 4; ++i)
                a[i] = *(const float4*)&As[(trow * 4 + i) * APAD + kk + k2];
#pragma unroll
            for (int q = 0; q < 4; ++q) {
                float4 b0 = *(const float4*)&Ws[(k2 + q) * H + tcol * 8];
                float4 b1 = *(const float4*)&Ws[(k2 + q) * H + tcol * 8 + 4];
                float bv[8] = {b0.x, b0.y, b0.z, b0.w, b1.x, b1.y, b1.z, b1.w};
#pragma unroll
                for (int i = 0; i < 4; ++i) {
                    float av = ((const float*)&a[i])[q];
#pragma unroll
                    for (int j = 0; j < 8; ++j)
                        acc[i][j] = fmaf(av, bv[j], acc[i][j]);
                }
            }
        }
    }
}

// Fill As[64][APAD] (128 cols) from a row-major [*, 128] global tensor.
__device__ __forceinline__ void fill_tile128(float* __restrict__ As,
                                             const float* __restrict__ src,
                                             long row0, int nrows) {
#pragma unroll
    for (int it = 0; it < 8; ++it) {
        int idx = it * 256 + threadIdx.x;      // over 64*32 float4 chunks
        int r = idx >> 5;
        int c4 = idx & 31;
        float4 v = make_float4(0.f, 0.f, 0.f, 0.f);
        if (r < nrows) v = *(const float4*)&src[(row0 + r) * H + c4 * 4];
        *(float4*)&As[r * APAD + c4 * 4] = v;
    }
}

// Store a thread's 4x8 micro-tile into As (callers sync before this).
__device__ __forceinline__ void store_tile(float* __restrict__ As, int trow,
                                           int tcol, const float v[4][8]) {
#pragma unroll
    for (int i = 0; i < 4; ++i) {
        *(float4*)&As[(trow * 4 + i) * APAD + tcol * 8] =
            make_float4(v[i][0], v[i][1], v[i][2], v[i][3]);
        *(float4*)&As[(trow * 4 + i) * APAD + tcol * 8 + 4] =
            make_float4(v[i][4], v[i][5], v[i][6], v[i][7]);
    }
}

// ---------------------------------------------------------------------------
__global__ void zero_m_kernel(int n4) {
    float4 z = make_float4(0.f, 0.f, 0.f, 0.f);
    for (int idx = blockIdx.x * blockDim.x + threadIdx.x; idx < n4;
         idx += gridDim.x * blockDim.x)
        ((float4*)g_m)[idx] = z;
}

// K1: edge_down = silu( (silu(x@Wkj+bkj) * silu(rbf@Wr2+br2)) @ Wdown + bdown )
__global__ __launch_bounds__(256) void edge_kernel(
    const float* __restrict__ x, const float* __restrict__ rbf,
    const float* __restrict__ W_kj, const float* __restrict__ b_kj,
    const float* __restrict__ W_rbf2, const float* __restrict__ b_rbf2,
    const float* __restrict__ W_down, const float* __restrict__ b_down,
    int E) {
    __shared__ __align__(16) float As[ROWS * APAD];
    __shared__ __align__(16) float Ws[16 * H];
    const int tid = threadIdx.x;
    const int trow = tid >> 4, tcol = tid & 15;
    const long e0 = (long)blockIdx.x * ROWS;
    const int rows = (int)min((long)ROWS, (long)E - e0);

    float acc[4][8];

    // t1 = silu(x @ W_kj + b_kj)
    fill_tile128(As, x, e0, rows);
#pragma unroll
    for (int i = 0; i < 4; ++i)
#pragma unroll
        for (int j = 0; j < 8; ++j) acc[i][j] = 0.f;
    gemm_tile<128>(As, Ws, W_kj, 128, trow, tcol, acc);
    float4 bk0 = *(const float4*)&b_kj[tcol * 8];
    float4 bk1 = *(const float4*)&b_kj[tcol * 8 + 4];
    float bk[8] = {bk0.x, bk0.y, bk0.z, bk0.w, bk1.x, bk1.y, bk1.z, bk1.w};
    float t1[4][8];
#pragma unroll
    for (int i = 0; i < 4; ++i)
#pragma unroll
        for (int j = 0; j < 8; ++j) t1[i][j] = silu(acc[i][j] + bk[j]);

    // t2 = silu(rbf @ W_rbf2 + b_rbf2);  h = t1 * t2
    __syncthreads();
    fill_tile128(As, rbf, e0, rows);
#pragma unroll
    for (int i = 0; i < 4; ++i)
#pragma unroll
        for (int j = 0; j < 8; ++j) acc[i][j] = 0.f;
    gemm_tile<128>(As, Ws, W_rbf2, 128, trow, tcol, acc);
    float4 br0 = *(const float4*)&b_rbf2[tcol * 8];
    float4 br1 = *(const float4*)&b_rbf2[tcol * 8 + 4];
    float br[8] = {br0.x, br0.y, br0.z, br0.w, br1.x, br1.y, br1.z, br1.w};
#pragma unroll
    for (int i = 0; i < 4; ++i)
#pragma unroll
        for (int j = 0; j < 8; ++j)
            t1[i][j] = t1[i][j] * silu(acc[i][j] + br[j]);

    // edge_down = silu(h @ W_down + b_down)
    __syncthreads();
    store_tile(As, trow, tcol, t1);
#pragma unroll
    for (int i = 0; i < 4; ++i)
#pragma unroll
        for (int j = 0; j < 8; ++j) acc[i][j] = 0.f;
    gemm_tile<128>(As, Ws, W_down, 128, trow, tcol, acc);
    float4 bd0 = *(const float4*)&b_down[tcol * 8];
    float4 bd1 = *(const float4*)&b_down[tcol * 8 + 4];
    float bd[8] = {bd0.x, bd0.y, bd0.z, bd0.w, bd1.x, bd1.y, bd1.z, bd1.w};
#pragma unroll
    for (int i = 0; i < 4; ++i) {
        int r = trow * 4 + i;
        if (r < rows) {
            float o[8];
#pragma unroll
            for (int j = 0; j < 8; ++j) o[j] = silu(acc[i][j] + bd[j]);
            float* dst = &g_edge_down[(e0 + r) * H + tcol * 8];
            *(float4*)dst = make_float4(o[0], o[1], o[2], o[3]);
            *(float4*)(dst + 4) = make_float4(o[4], o[5], o[6], o[7]);
        }
    }
}

// K2: per triplet: s = silu(silu(sbf@Wsbf1)@Wsbf2);
//     o = silu((edge_down[idx_kj] * s) @ W_up + b_up); scatter-add to g_m[idx_ji]
__global__ __launch_bounds__(256) void trip_kernel(
    const float* __restrict__ sbf, const int* __restrict__ idx_kj,
    const int* __restrict__ idx_ji, const float* __restrict__ W_sbf1,
    const float* __restrict__ W_sbf2, const float* __restrict__ W_up,
    const float* __restrict__ b_up, int T) {
    __shared__ __align__(16) float As[ROWS * APAD];
    __shared__ __align__(16) float Ws[16 * H];
    __shared__ int skj[ROWS], sji[ROWS];
    const int tid = threadIdx.x;
    const int trow = tid >> 4, tcol = tid & 15;
    const long t0 = (long)blockIdx.x * ROWS;
    const int rows = (int)min((long)ROWS, (long)T - t0);

    if (tid < ROWS) {
        long t = t0 + tid;
        skj[tid] = (tid < rows) ? idx_kj[t] : 0;
        sji[tid] = (tid < rows) ? idx_ji[t] : 0;
    }

    // Fill sbf tile: [64 x 48] (cols 42..47 zero)
    for (int idx = tid; idx < ROWS * 48; idx += 256) {
        int r = idx / 48, c = idx - r * 48;
        As[r * APAD + c] =
            (c < 42 && r < rows) ? sbf[(t0 + r) * 42 + c] : 0.f;
    }

    float acc[4][8];
#pragma unroll
    for (int i = 0; i < 4; ++i)
#pragma unroll
        for (int j = 0; j < 8; ++j) acc[i][j] = 0.f;
    gemm_tile<48>(As, Ws, W_sbf1, 42, trow, tcol, acc);
    float v[4][8];
#pragma unroll
    for (int i = 0; i < 4; ++i)
#pragma unroll
        for (int j = 0; j < 8; ++j) v[i][j] = silu(acc[i][j]);

    __syncthreads();
    store_tile(As, trow, tcol, v);
#pragma unroll
    for (int i = 0; i < 4; ++i)
#pragma unroll
        for (int j = 0; j < 8; ++j) acc[i][j] = 0.f;
    gemm_tile<128>(As, Ws, W_sbf2, 128, trow, tcol, acc);

    // s * gathered edge_down
#pragma unroll
    for (int i = 0; i < 4; ++i) {
        int r = trow * 4 + i;
        long ei = (long)skj[r];
        const float* gp = &g_edge_down[ei * H + tcol * 8];
        float4 g0 = *(const float4*)gp;
        float4 g1 = *(const float4*)(gp + 4);
        float gv[8] = {g0.x, g0.y, g0.z, g0.w, g1.x, g1.y, g1.z, g1.w};
#pragma unroll
        for (int j = 0; j < 8; ++j) v[i][j] = silu(acc[i][j]) * gv[j];
    }

    __syncthreads();
    store_tile(As, trow, tcol, v);
#pragma unroll
    for (int i = 0; i < 4; ++i)
#pragma unroll
        for (int j = 0; j < 8; ++j) acc[i][j] = 0.f;
    gemm_tile<128>(As, Ws, W_up, 128, trow, tcol, acc);

    float4 bu0 = *(const float4*)&b_up[tcol * 8];
    float4 bu1 = *(const float4*)&b_up[tcol * 8 + 4];
    float bu[8] = {bu0.x, bu0.y, bu0.z, bu0.w, bu1.x, bu1.y, bu1.z, bu1.w};
#pragma unroll
    for (int i = 0; i < 4; ++i) {
        int r = trow * 4 + i;
        if (r < rows) {
            float o[8];
#pragma unroll
            for (int j = 0; j < 8; ++j) o[j] = silu(acc[i][j] + bu[j]);
            float* p = &g_m[(long)sji[r] * H + tcol * 8];
            asm volatile(
                "red.global.add.v4.f32 [%0], {%1,%2,%3,%4};" ::"l"(p),
                "f"(o[0]), "f"(o[1]), "f"(o[2]), "f"(o[3])
                : "memory");
            asm volatile(
                "red.global.add.v4.f32 [%0], {%1,%2,%3,%4};" ::"l"(p + 4),
                "f"(o[4]), "f"(o[5]), "f"(o[6]), "f"(o[7])
                : "memory");
        }
    }
}

// K3: out = m + silu(silu(m@Wr1a+br1a)@Wr1b+br1b) + x
__global__ __launch_bounds__(256) void res_kernel(
    const float* __restrict__ x, const float* __restrict__ W_r1a,
    const float* __restrict__ b_r1a, const float* __restrict__ W_r1b,
    const float* __restrict__ b_r1b, float* __restrict__ out, int E) {
    __shared__ __align__(16) float As[ROWS * APAD];
    __shared__ __align__(16) float Ws[16 * H];
    const int tid = threadIdx.x;
    const int trow = tid >> 4, tcol = tid & 15;
    const long e0 = (long)blockIdx.x * ROWS;
    const int rows = (int)min((long)ROWS, (long)E - e0);

    float acc[4][8];
    fill_tile128(As, g_m, e0, rows);
#pragma unroll
    for (int i = 0; i < 4; ++i)
#pragma unroll
        for (int j = 0; j < 8; ++j) acc[i][j] = 0.f;
    gemm_tile<128>(As, Ws, W_r1a, 128, trow, tcol, acc);
    float4 ba0 = *(const float4*)&b_r1a[tcol * 8];
    float4 ba1 = *(const float4*)&b_r1a[tcol * 8 + 4];
    float ba[8] = {ba0.x, ba0.y, ba0.z, ba0.w, ba1.x, ba1.y, ba1.z, ba1.w};
    float v[4][8];
#pragma unroll
    for (int i = 0; i < 4; ++i)
#pragma unroll
        for (int j = 0; j < 8; ++j) v[i][j] = silu(acc[i][j] + ba[j]);

    __syncthreads();
    store_tile(As, trow, tcol, v);
#pragma unroll
    for (int i = 0; i < 4; ++i)
#pragma unroll
        for (int j = 0; j < 8; ++j) acc[i][j] = 0.f;
    gemm_tile<128>(As, Ws, W_r1b, 128, trow, tcol, acc);

    float4 bb0 = *(const float4*)&b_r1b[tcol * 8];
    float4 bb1 = *(const float4*)&b_r1b[tcol * 8 + 4];
    float bb[8] = {bb0.x, bb0.y, bb0.z, bb0.w, bb1.x, bb1.y, bb1.z, bb1.w};
#pragma unroll
    for (int i = 0; i < 4; ++i) {
        int r = trow * 4 + i;
        if (r < rows) {
            const float* mp = &g_m[(e0 + r) * H + tcol * 8];
            const float* xp = &x[(e0 + r) * H + tcol * 8];
            float4 m0 = *(const float4*)mp;
            float4 m1 = *(const float4*)(mp + 4);
            float4 x0 = *(const float4*)xp;
            float4 x1 = *(const float4*)(xp + 4);
            float mv[8] = {m0.x, m0.y, m0.z, m0.w, m1.x, m1.y, m1.z, m1.w};
            float xv[8] = {x0.x, x0.y, x0.z, x0.w, x1.x, x1.y, x1.z, x1.w};
            float o[8];
#pragma unroll
            for (int j = 0; j < 8; ++j)
                o[j] = mv[j] + silu(acc[i][j] + bb[j]) + xv[j];
            float* dst = &out[(e0 + r) * H + tcol * 8];
            *(float4*)dst = make_float4(o[0], o[1], o[2], o[3]);
            *(float4*)(dst + 4) = make_float4(o[4], o[5], o[6], o[7]);
        }
    }
}

// ---------------------------------------------------------------------------
extern "C" void kernel_launch(void* const* d_in, const int* in_sizes, int n_in,
                              void* d_out, int out_size) {
    const float* x      = (const float*)d_in[0];
    const float* rbf    = (const float*)d_in[1];
    const float* sbf    = (const float*)d_in[2];
    const int* idx_kj   = (const int*)d_in[3];
    const int* idx_ji   = (const int*)d_in[4];
    const float* W_rbf2 = (const float*)d_in[5];
    const float* b_rbf2 = (const float*)d_in[6];
    const float* W_sbf1 = (const float*)d_in[7];
    const float* W_sbf2 = (const float*)d_in[8];
    const float* W_kj   = (const float*)d_in[9];
    const float* b_kj   = (const float*)d_in[10];
    const float* W_down = (const float*)d_in[11];
    const float* b_down = (const float*)d_in[12];
    const float* W_up   = (const float*)d_in[13];
    const float* b_up   = (const float*)d_in[14];
    const float* W_r1a  = (const float*)d_in[15];
    const float* b_r1a  = (const float*)d_in[16];
    const float* W_r1b  = (const float*)d_in[17];
    const float* b_r1b  = (const float*)d_in[18];
    float* out = (float*)d_out;

    int E = in_sizes[0] / H;
    int T = in_sizes[3];

    zero_m_kernel<<<2048, 256>>>(E * (H / 4));
    edge_kernel<<<(E + ROWS - 1) / ROWS, 256>>>(x, rbf, W_kj, b_kj, W_rbf2,
                                                b_rbf2, W_down, b_down, E);
    trip_kernel<<<(T + ROWS - 1) / ROWS, 256>>>(sbf, idx_kj, idx_ji, W_sbf1,
                                                W_sbf2, W_up, b_up, T);
    res_kernel<<<(E + ROWS - 1) / ROWS, 256>>>(x, W_r1a, b_r1a, W_r1b, b_r1b,
                                               out, E);
}

// round 3
// speedup vs baseline: 3.7649x; 3.7649x over previous
#include <cuda_runtime.h>
#include <cuda_bf16.h>
#include <cstdint>

#define H 128
#define MT 128
#define MAX_E 250000

#define SA128 136          // bf16 stride for K=128 tiles
#define SA64  72           // bf16 stride for K=64 tiles
#define SD    132          // float stride for D buffer

// smem offsets (bytes)
#define OFF_AH 0u
#define OFF_AL 34816u
#define OFF_BH 69632u
#define OFF_BL 104448u
#define OFF_D  69632u      // overlays B (used strictly after mma reads B)
#define OFF_T1 139264u
#define OFF_KJ 204800u
#define OFF_JI 205312u
#define SMEM_BYTES 205824

// ---------------- scratch ---------------------------------------------------
__device__ __align__(16) __nv_bfloat16 g_WH[7 * 16384];   // [mat][n][k] k=128
__device__ __align__(16) __nv_bfloat16 g_WL[7 * 16384];
__device__ __align__(16) __nv_bfloat16 g_W1H[8192];       // sbf1 [n][64]
__device__ __align__(16) __nv_bfloat16 g_W1L[8192];
__device__ __align__(16) __nv_bfloat16 g_edge_hi[(size_t)MAX_E * H];
__device__ __align__(16) __nv_bfloat16 g_edge_lo[(size_t)MAX_E * H];
__device__ __align__(16) float        g_m[(size_t)MAX_E * H];

// ---------------- numeric helpers -------------------------------------------
__device__ __forceinline__ void sp(float v, float& h, float& l) {
    h = __bfloat162float(__float2bfloat16(v));
    l = v - h;
}
__device__ __forceinline__ uint32_t pk2(float a, float b) {
    __nv_bfloat162 t = __floats2bfloat162_rn(a, b);
    return *(uint32_t*)&t;
}

// MUFU-free silu: sigmoid via exp2(poly)+bit-scale, rcp via Newton.
__device__ __forceinline__ float fast_silu(float x) {
    float t = x * -1.4426950408889634f;            // -x*log2(e)
    t = fminf(fmaxf(t, -126.0f), 126.0f);
    float s = __fadd_rn(t, 12582912.0f);           // round to nearest int
    int   sb = __float_as_int(s);
    float fi = __fadd_rn(s, -12582912.0f);
    float f  = t - fi;                             // [-0.5, 0.5]
    float p = 1.5404e-4f;
    p = fmaf(p, f, 1.3333558e-3f);
    p = fmaf(p, f, 9.6181291e-3f);
    p = fmaf(p, f, 5.5504109e-2f);
    p = fmaf(p, f, 2.4022651e-1f);
    p = fmaf(p, f, 6.9314718e-1f);
    p = fmaf(p, f, 1.0f);
    float scale = __int_as_float(0x3F800000 + ((sb - 0x4B400000) << 23)); // 2^i
    float e = p * scale;                           // exp(-x)
    float d = 1.0f + e;
    float r = __int_as_float(0x7EF311C3u - (uint32_t)__float_as_int(d));
    r = r * fmaf(-d, r, 2.0f);
    r = r * fmaf(-d, r, 2.0f);
    r = r * fmaf(-d, r, 2.0f);                     // 1/(1+exp(-x))
    return x * r;
}

// ---------------- mma.sync --------------------------------------------------
__device__ __forceinline__ void mma_bf16(float* d, const uint32_t* a, const uint32_t* b) {
    asm volatile(
        "mma.sync.aligned.m16n8k16.row.col.f32.bf16.bf16.f32 "
        "{%0,%1,%2,%3}, {%4,%5,%6,%7}, {%8,%9}, {%0,%1,%2,%3};"
        : "+f"(d[0]), "+f"(d[1]), "+f"(d[2]), "+f"(d[3])
        : "r"(a[0]), "r"(a[1]), "r"(a[2]), "r"(a[3]), "r"(b[0]), "r"(b[1]));
}

// Warp computes its 64x32 subtile of the 128x128 CTA tile.
// A [128][KB] hi/lo and B [128][KB] hi/lo in smem, stride SA=KB+8 (bf16 units).
// 3-pass split: AhBh + AlBh + AhBl.
template <int KB, int SA>
__device__ __forceinline__ void warp_gemm(const char* sm, uint32_t oAh, uint32_t oAl,
                                          uint32_t oBh, uint32_t oBl,
                                          float (&acc)[4][4][4]) {
    const int lane = threadIdx.x & 31, w = threadIdx.x >> 5;
    const int wr = w >> 2, wc = w & 3;
    const int r4 = lane >> 2, kq = lane & 3;
    const int arow0 = wr * 64 + r4;
    const int bcol0 = wc * 32 + r4;
#pragma unroll
    for (int mi = 0; mi < 4; ++mi)
#pragma unroll
        for (int ni = 0; ni < 4; ++ni)
#pragma unroll
            for (int q = 0; q < 4; ++q) acc[mi][ni][q] = 0.f;

#pragma unroll
    for (int k0 = 0; k0 < KB; k0 += 16) {
        uint32_t ah[4][4], al[4][4], bh[4][2], bl[4][2];
#pragma unroll
        for (int mi = 0; mi < 4; ++mi) {
            int e = (arow0 + mi * 16) * SA + k0 + kq * 2;
            ah[mi][0] = *(const uint32_t*)(sm + oAh + 2 * e);
            ah[mi][1] = *(const uint32_t*)(sm + oAh + 2 * (e + 8 * SA));
            ah[mi][2] = *(const uint32_t*)(sm + oAh + 2 * (e + 8));
            ah[mi][3] = *(const uint32_t*)(sm + oAh + 2 * (e + 8 * SA + 8));
            al[mi][0] = *(const uint32_t*)(sm + oAl + 2 * e);
            al[mi][1] = *(const uint32_t*)(sm + oAl + 2 * (e + 8 * SA));
            al[mi][2] = *(const uint32_t*)(sm + oAl + 2 * (e + 8));
            al[mi][3] = *(const uint32_t*)(sm + oAl + 2 * (e + 8 * SA + 8));
        }
#pragma unroll
        for (int ni = 0; ni < 4; ++ni) {
            int e = (bcol0 + ni * 8) * SA + k0 + kq * 2;
            bh[ni][0] = *(const uint32_t*)(sm + oBh + 2 * e);
            bh[ni][1] = *(const uint32_t*)(sm + oBh + 2 * (e + 8));
            bl[ni][0] = *(const uint32_t*)(sm + oBl + 2 * e);
            bl[ni][1] = *(const uint32_t*)(sm + oBl + 2 * (e + 8));
        }
#pragma unroll
        for (int mi = 0; mi < 4; ++mi)
#pragma unroll
            for (int ni = 0; ni < 4; ++ni) mma_bf16(acc[mi][ni], ah[mi], bh[ni]);
#pragma unroll
        for (int mi = 0; mi < 4; ++mi)
#pragma unroll
            for (int ni = 0; ni < 4; ++ni) mma_bf16(acc[mi][ni], al[mi], bh[ni]);
#pragma unroll
        for (int mi = 0; mi < 4; ++mi)
#pragma unroll
            for (int ni = 0; ni < 4; ++ni) mma_bf16(acc[mi][ni], ah[mi], bl[ni]);
    }
}

__device__ __forceinline__ void acc_to_D(float* D, float (&acc)[4][4][4]) {
    const int lane = threadIdx.x & 31, w = threadIdx.x >> 5;
    const int wr = w >> 2, wc = w & 3;
    const int r4 = lane >> 2, kq = lane & 3;
#pragma unroll
    for (int mi = 0; mi < 4; ++mi) {
        int row = wr * 64 + mi * 16 + r4;
#pragma unroll
        for (int ni = 0; ni < 4; ++ni) {
            int col = wc * 32 + ni * 8 + kq * 2;
            *(float2*)&D[row * SD + col] = make_float2(acc[mi][ni][0], acc[mi][ni][1]);
            *(float2*)&D[(row + 8) * SD + col] = make_float2(acc[mi][ni][2], acc[mi][ni][3]);
        }
    }
}

// ---------------- fills / copies --------------------------------------------
__device__ __forceinline__ void split_store4(char* Ah, char* Al, int eoff, float4 v) {
    float h0, l0, h1, l1, h2, l2, h3, l3;
    sp(v.x, h0, l0); sp(v.y, h1, l1); sp(v.z, h2, l2); sp(v.w, h3, l3);
    *(uint2*)(Ah + 2 * eoff) = make_uint2(pk2(h0, h1), pk2(h2, h3));
    *(uint2*)(Al + 2 * eoff) = make_uint2(pk2(l0, l1), pk2(l2, l3));
}

__device__ __forceinline__ void fill_A128(char* Ah, char* Al,
                                          const float* __restrict__ src,
                                          long r0, int nrows) {
    for (int i = threadIdx.x; i < 4096; i += 256) {
        int r = i >> 5, c = (i & 31) * 4;
        float4 v = (r < nrows) ? *(const float4*)&src[(r0 + r) * H + c]
                               : make_float4(0.f, 0.f, 0.f, 0.f);
        split_store4(Ah, Al, r * SA128 + c, v);
    }
}

template <int KB>
__device__ __forceinline__ void copy_B(char* Bh, char* Bl,
                                       const __nv_bfloat16* __restrict__ sH,
                                       const __nv_bfloat16* __restrict__ sL) {
    const int SEG = KB / 8;
    for (int i = threadIdx.x; i < 128 * SEG; i += 256) {
        int r = i / SEG, s = i - r * SEG;
        *(uint4*)(Bh + (r * (KB + 8) + s * 8) * 2) = ((const uint4*)sH)[i];
        *(uint4*)(Bl + (r * (KB + 8) + s * 8) * 2) = ((const uint4*)sL)[i];
    }
}

// ---------------- small kernels ---------------------------------------------
__global__ void zero_m_kernel(size_t n4) {
    float4 z = make_float4(0.f, 0.f, 0.f, 0.f);
    for (size_t i = (size_t)blockIdx.x * blockDim.x + threadIdx.x; i < n4;
         i += (size_t)gridDim.x * blockDim.x)
        ((float4*)g_m)[i] = z;
}

__global__ void prep_kernel(const float* __restrict__ Wkj, const float* __restrict__ Wrbf2,
                            const float* __restrict__ Wdown, const float* __restrict__ Wsbf2,
                            const float* __restrict__ Wup, const float* __restrict__ Wr1a,
                            const float* __restrict__ Wr1b, const float* __restrict__ Wsbf1) {
    int idx = blockIdx.x * 256 + threadIdx.x;
    if (idx < 7 * 16384) {
        int mat = idx >> 14, rem = idx & 16383;
        int n = rem >> 7, k = rem & 127;
        const float* Ws[7] = {Wkj, Wrbf2, Wdown, Wsbf2, Wup, Wr1a, Wr1b};
        float v = Ws[mat][k * H + n];        // B[n][k] = W[k][n]
        float h, l; sp(v, h, l);
        g_WH[idx] = __float2bfloat16(h);
        g_WL[idx] = __float2bfloat16(l);
    } else {
        int rem = idx - 7 * 16384;
        if (rem < 8192) {
            int n = rem >> 6, k = rem & 63;
            float v = (k < 42) ? Wsbf1[k * H + n] : 0.f;
            float h, l; sp(v, h, l);
            g_W1H[rem] = __float2bfloat16(h);
            g_W1L[rem] = __float2bfloat16(l);
        }
    }
}

// ---------------- main kernels ----------------------------------------------
// K1: edge_down = silu((silu(x@Wkj+b)*silu(rbf@Wr2+b))@Wdown+b) -> split bf16
__global__ __launch_bounds__(256, 1)
void edge_kernel(const float* __restrict__ x, const float* __restrict__ rbf,
                 const float* __restrict__ b_kj, const float* __restrict__ b_rbf2,
                 const float* __restrict__ b_down, int E) {
    extern __shared__ __align__(16) char sm[];
    char* Ah = sm + OFF_AH; char* Al = sm + OFF_AL;
    char* Bh = sm + OFF_BH; char* Bl = sm + OFF_BL;
    float* D = (float*)(sm + OFF_D);
    float* T1 = (float*)(sm + OFF_T1);
    const int tid = threadIdx.x;
    const int row = tid >> 1, c0 = (tid & 1) * 64;
    const long e0 = (long)blockIdx.x * MT;
    const int rows = (int)min((long)MT, (long)E - e0);
    float acc[4][4][4];

    // S0: x @ Wkj -> T1 = silu(.+b_kj)
    fill_A128(Ah, Al, x, e0, rows);
    copy_B<128>(Bh, Bl, g_WH + 0 * 16384, g_WL + 0 * 16384);
    __syncthreads();
    warp_gemm<128, SA128>(sm, OFF_AH, OFF_AL, OFF_BH, OFF_BL, acc);
    __syncthreads();
    acc_to_D(D, acc);
    __syncthreads();
#pragma unroll
    for (int g = 0; g < 16; ++g) {
        float4 d = *(const float4*)&D[row * SD + c0 + g * 4];
        float4 b = *(const float4*)&b_kj[c0 + g * 4];
        float4 o;
        o.x = fast_silu(d.x + b.x); o.y = fast_silu(d.y + b.y);
        o.z = fast_silu(d.z + b.z); o.w = fast_silu(d.w + b.w);
        *(float4*)&T1[row * H + c0 + g * 4] = o;
    }
    __syncthreads();

    // S1: rbf @ Wrbf2 ; h = T1 * silu(.+b_rbf2) -> split into A
    fill_A128(Ah, Al, rbf, e0, rows);
    copy_B<128>(Bh, Bl, g_WH + 1 * 16384, g_WL + 1 * 16384);
    __syncthreads();
    warp_gemm<128, SA128>(sm, OFF_AH, OFF_AL, OFF_BH, OFF_BL, acc);
    __syncthreads();
    acc_to_D(D, acc);
    __syncthreads();
#pragma unroll
    for (int g = 0; g < 16; ++g) {
        float4 d = *(const float4*)&D[row * SD + c0 + g * 4];
        float4 b = *(const float4*)&b_rbf2[c0 + g * 4];
        float4 t = *(const float4*)&T1[row * H + c0 + g * 4];
        float4 h;
        h.x = t.x * fast_silu(d.x + b.x); h.y = t.y * fast_silu(d.y + b.y);
        h.z = t.z * fast_silu(d.z + b.z); h.w = t.w * fast_silu(d.w + b.w);
        split_store4(Ah, Al, row * SA128 + c0 + g * 4, h);
    }
    __syncthreads();

    // S2: h @ Wdown -> silu(.+b_down) -> g_edge hi/lo
    copy_B<128>(Bh, Bl, g_WH + 2 * 16384, g_WL + 2 * 16384);
    __syncthreads();
    warp_gemm<128, SA128>(sm, OFF_AH, OFF_AL, OFF_BH, OFF_BL, acc);
    __syncthreads();
    acc_to_D(D, acc);
    __syncthreads();
    if (row < rows) {
        __nv_bfloat16* oh = g_edge_hi + (size_t)(e0 + row) * H + c0;
        __nv_bfloat16* ol = g_edge_lo + (size_t)(e0 + row) * H + c0;
#pragma unroll
        for (int g = 0; g < 16; ++g) {
            float4 d = *(const float4*)&D[row * SD + c0 + g * 4];
            float4 b = *(const float4*)&b_down[c0 + g * 4];
            float o0 = fast_silu(d.x + b.x), o1 = fast_silu(d.y + b.y);
            float o2 = fast_silu(d.z + b.z), o3 = fast_silu(d.w + b.w);
            float h0, l0, h1, l1, h2, l2, h3, l3;
            sp(o0, h0, l0); sp(o1, h1, l1); sp(o2, h2, l2); sp(o3, h3, l3);
            *(uint2*)(oh + g * 4) = make_uint2(pk2(h0, h1), pk2(h2, h3));
            *(uint2*)(ol + g * 4) = make_uint2(pk2(l0, l1), pk2(l2, l3));
        }
    }
}

// K2: s=silu(silu(sbf@W1)@W2); o=silu((edge[idx_kj]*s)@Wup+b); red.add -> g_m[idx_ji]
__global__ __launch_bounds__(256, 1)
void trip_kernel(const float* __restrict__ sbf, const int* __restrict__ idx_kj,
                 const int* __restrict__ idx_ji, const float* __restrict__ b_up, int T) {
    extern __shared__ __align__(16) char sm[];
    char* Ah = sm + OFF_AH; char* Al = sm + OFF_AL;
    char* Bh = sm + OFF_BH; char* Bl = sm + OFF_BL;
    float* D = (float*)(sm + OFF_D);
    int* skj = (int*)(sm + OFF_KJ);
    int* sji = (int*)(sm + OFF_JI);
    const int tid = threadIdx.x;
    const int row = tid >> 1, c0 = (tid & 1) * 64;
    const long t0 = (long)blockIdx.x * MT;
    const int rows = (int)min((long)MT, (long)T - t0);
    float acc[4][4][4];

    if (tid < MT) {
        long t = t0 + tid;
        skj[tid] = (tid < rows) ? idx_kj[t] : 0;
        sji[tid] = (tid < rows) ? idx_ji[t] : 0;
    }

    // S0: sbf @ Wsbf1 (K=64, cols 42..63 zero)
    for (int i = tid; i < 8192; i += 256) {
        int r = i >> 6, c = i & 63;
        float v = (c < 42 && r < rows) ? sbf[(t0 + r) * 42 + c] : 0.f;
        float h, l; sp(v, h, l);
        *(__nv_bfloat16*)(Ah + (r * SA64 + c) * 2) = __float2bfloat16(h);
        *(__nv_bfloat16*)(Al + (r * SA64 + c) * 2) = __float2bfloat16(l);
    }
    copy_B<64>(Bh, Bl, g_W1H, g_W1L);
    __syncthreads();
    warp_gemm<64, SA64>(sm, OFF_AH, OFF_AL, OFF_BH, OFF_BL, acc);
    __syncthreads();
    acc_to_D(D, acc);
    __syncthreads();
#pragma unroll
    for (int g = 0; g < 16; ++g) {
        float4 d = *(const float4*)&D[row * SD + c0 + g * 4];
        float4 o;
        o.x = fast_silu(d.x); o.y = fast_silu(d.y);
        o.z = fast_silu(d.z); o.w = fast_silu(d.w);
        split_store4(Ah, Al, row * SA128 + c0 + g * 4, o);
    }
    __syncthreads();

    // S1: @ Wsbf2 ; multiply gathered edge_down -> split into A
    copy_B<128>(Bh, Bl, g_WH + 3 * 16384, g_WL + 3 * 16384);
    __syncthreads();
    warp_gemm<128, SA128>(sm, OFF_AH, OFF_AL, OFF_BH, OFF_BL, acc);
    __syncthreads();
    acc_to_D(D, acc);
    __syncthreads();
    {
        size_t e = (size_t)skj[row];
        const __nv_bfloat16* gh = g_edge_hi + e * H + c0;
        const __nv_bfloat16* gl = g_edge_lo + e * H + c0;
#pragma unroll
        for (int g = 0; g < 16; ++g) {
            float4 d = *(const float4*)&D[row * SD + c0 + g * 4];
            uint2 uh = *(const uint2*)(gh + g * 4);
            uint2 ul = *(const uint2*)(gl + g * 4);
            __nv_bfloat162 h01 = *(__nv_bfloat162*)&uh.x;
            __nv_bfloat162 h23 = *(__nv_bfloat162*)&uh.y;
            __nv_bfloat162 l01 = *(__nv_bfloat162*)&ul.x;
            __nv_bfloat162 l23 = *(__nv_bfloat162*)&ul.y;
            float4 o;
            o.x = fast_silu(d.x) * (__bfloat162float(h01.x) + __bfloat162float(l01.x));
            o.y = fast_silu(d.y) * (__bfloat162float(h01.y) + __bfloat162float(l01.y));
            o.z = fast_silu(d.z) * (__bfloat162float(h23.x) + __bfloat162float(l23.x));
            o.w = fast_silu(d.w) * (__bfloat162float(h23.y) + __bfloat162float(l23.y));
            split_store4(Ah, Al, row * SA128 + c0 + g * 4, o);
        }
    }
    __syncthreads();

    // S2: @ Wup -> silu(.+b_up) -> scatter-add
    copy_B<128>(Bh, Bl, g_WH + 4 * 16384, g_WL + 4 * 16384);
    __syncthreads();
    warp_gemm<128, SA128>(sm, OFF_AH, OFF_AL, OFF_BH, OFF_BL, acc);
    __syncthreads();
    acc_to_D(D, acc);
    __syncthreads();
    if (row < rows) {
        float* mp = g_m + (size_t)sji[row] * H + c0;
#pragma unroll
        for (int g = 0; g < 16; ++g) {
            float4 d = *(const float4*)&D[row * SD + c0 + g * 4];
            float4 b = *(const float4*)&b_up[c0 + g * 4];
            float o0 = fast_silu(d.x + b.x), o1 = fast_silu(d.y + b.y);
            float o2 = fast_silu(d.z + b.z), o3 = fast_silu(d.w + b.w);
            asm volatile("red.global.add.v4.f32 [%0], {%1,%2,%3,%4};"
                         :: "l"(mp + g * 4), "f"(o0), "f"(o1), "f"(o2), "f"(o3)
                         : "memory");
        }
    }
}

// K3: out = m + silu(silu(m@Wr1a+b)@Wr1b+b) + x
__global__ __launch_bounds__(256, 1)
void res_kernel(const float* __restrict__ x, const float* __restrict__ b_r1a,
                const float* __restrict__ b_r1b, float* __restrict__ out, int E) {
    extern __shared__ __align__(16) char sm[];
    char* Ah = sm + OFF_AH; char* Al = sm + OFF_AL;
    char* Bh = sm + OFF_BH; char* Bl = sm + OFF_BL;
    float* D = (float*)(sm + OFF_D);
    const int tid = threadIdx.x;
    const int row = tid >> 1, c0 = (tid & 1) * 64;
    const long e0 = (long)blockIdx.x * MT;
    const int rows = (int)min((long)MT, (long)E - e0);
    float acc[4][4][4];

    // S0: m @ Wr1a
    fill_A128(Ah, Al, g_m, e0, rows);
    copy_B<128>(Bh, Bl, g_WH + 5 * 16384, g_WL + 5 * 16384);
    __syncthreads();
    warp_gemm<128, SA128>(sm, OFF_AH, OFF_AL, OFF_BH, OFF_BL, acc);
    __syncthreads();
    acc_to_D(D, acc);
    __syncthreads();
#pragma unroll
    for (int g = 0; g < 16; ++g) {
        float4 d = *(const float4*)&D[row * SD + c0 + g * 4];
        float4 b = *(const float4*)&b_r1a[c0 + g * 4];
        float4 o;
        o.x = fast_silu(d.x + b.x); o.y = fast_silu(d.y + b.y);
        o.z = fast_silu(d.z + b.z); o.w = fast_silu(d.w + b.w);
        split_store4(Ah, Al, row * SA128 + c0 + g * 4, o);
    }
    __syncthreads();

    // S1: @ Wr1b ; out = m + silu(.+b) + x
    copy_B<128>(Bh, Bl, g_WH + 6 * 16384, g_WL + 6 * 16384);
    __syncthreads();
    warp_gemm<128, SA128>(sm, OFF_AH, OFF_AL, OFF_BH, OFF_BL, acc);
    __syncthreads();
    acc_to_D(D, acc);
    __syncthreads();
    if (row < rows) {
        const float4* mp = (const float4*)(g_m + (size_t)(e0 + row) * H + c0);
        const float4* xp = (const float4*)(x + (size_t)(e0 + row) * H + c0);
        float4* op = (float4*)(out + (size_t)(e0 + row) * H + c0);
#pragma unroll
        for (int g = 0; g < 16; ++g) {
            float4 d = *(const float4*)&D[row * SD + c0 + g * 4];
            float4 b = *(const float4*)&b_r1b[c0 + g * 4];
            float4 mv = mp[g], xv = xp[g], o;
            o.x = mv.x + fast_silu(d.x + b.x) + xv.x;
            o.y = mv.y + fast_silu(d.y + b.y) + xv.y;
            o.z = mv.z + fast_silu(d.z + b.z) + xv.z;
            o.w = mv.w + fast_silu(d.w + b.w) + xv.w;
            op[g] = o;
        }
    }
}

// ---------------------------------------------------------------------------
extern "C" void kernel_launch(void* const* d_in, const int* in_sizes, int n_in,
                              void* d_out, int out_size) {
    const float* x      = (const float*)d_in[0];
    const float* rbf    = (const float*)d_in[1];
    const float* sbf    = (const float*)d_in[2];
    const int*   idx_kj = (const int*)d_in[3];
    const int*   idx_ji = (const int*)d_in[4];
    const float* W_rbf2 = (const float*)d_in[5];
    const float* b_rbf2 = (const float*)d_in[6];
    const float* W_sbf1 = (const float*)d_in[7];
    const float* W_sbf2 = (const float*)d_in[8];
    const float* W_kj   = (const float*)d_in[9];
    const float* b_kj   = (const float*)d_in[10];
    const float* W_down = (const float*)d_in[11];
    const float* b_down = (const float*)d_in[12];
    const float* W_up   = (const float*)d_in[13];
    const float* b_up   = (const float*)d_in[14];
    const float* W_r1a  = (const float*)d_in[15];
    const float* b_r1a  = (const float*)d_in[16];
    const float* W_r1b  = (const float*)d_in[17];
    const float* b_r1b  = (const float*)d_in[18];
    float* out = (float*)d_out;

    int E = in_sizes[0] / H;
    int T = in_sizes[3];

    static bool attr_done = false;
    if (!attr_done) {
        cudaFuncSetAttribute(edge_kernel, cudaFuncAttributeMaxDynamicSharedMemorySize, SMEM_BYTES);
        cudaFuncSetAttribute(trip_kernel, cudaFuncAttributeMaxDynamicSharedMemorySize, SMEM_BYTES);
        cudaFuncSetAttribute(res_kernel, cudaFuncAttributeMaxDynamicSharedMemorySize, SMEM_BYTES);
        attr_done = true;
    }

    prep_kernel<<<480, 256>>>(W_kj, W_rbf2, W_down, W_sbf2, W_up, W_r1a, W_r1b, W_sbf1);
    zero_m_kernel<<<2048, 256>>>((size_t)E * H / 4);
    edge_kernel<<<(E + MT - 1) / MT, 256, SMEM_BYTES>>>(x, rbf, b_kj, b_rbf2, b_down, E);
    trip_kernel<<<(T + MT - 1) / MT, 256, SMEM_BYTES>>>(sbf, idx_kj, idx_ji, b_up, T);
    res_kernel<<<(E + MT - 1) / MT, 256, SMEM_BYTES>>>(x, b_r1a, b_r1b, out, E);
}

// round 5
// speedup vs baseline: 4.5050x; 1.1966x over previous
#include <cuda_runtime.h>
#include <cuda_bf16.h>
#include <cstdint>

#define H 128
#define MT 64              // rows per CTA tile (halved for 2 CTAs/SM)
#define MAX_E 250000

#define SA128 136          // bf16 stride for K=128 tiles
#define SA64  72           // bf16 stride for K=64 tiles
#define SD    132          // float stride for D buffer

// smem offsets (bytes)
#define OFF_AH 0u
#define OFF_AL 17408u      // 64*136*2
#define OFF_BH 34816u
#define OFF_BL 69632u
#define OFF_D  34816u      // overlays B-hi (used strictly after mma reads B)
#define OFF_KJ 104448u
#define OFF_JI 104704u
#define SMEM_BYTES 105472

// ---------------- scratch ---------------------------------------------------
__device__ __align__(16) __nv_bfloat16 g_WH[7 * 16384];   // [mat][n][k] k=128
__device__ __align__(16) __nv_bfloat16 g_WL[7 * 16384];
__device__ __align__(16) __nv_bfloat16 g_W1H[8192];       // sbf1 [n][64]
__device__ __align__(16) __nv_bfloat16 g_W1L[8192];
__device__ __align__(16) __nv_bfloat16 g_edge_hi[(size_t)MAX_E * H];
__device__ __align__(16) __nv_bfloat16 g_edge_lo[(size_t)MAX_E * H];
__device__ __align__(16) float        g_m[(size_t)MAX_E * H];

// ---------------- numeric helpers -------------------------------------------
__device__ __forceinline__ void sp(float v, float& h, float& l) {
    h = __bfloat162float(__float2bfloat16(v));
    l = v - h;
}
__device__ __forceinline__ uint32_t pk2(float a, float b) {
    __nv_bfloat162 t = __floats2bfloat162_rn(a, b);
    return *(uint32_t*)&t;
}

// MUFU-free silu: sigmoid via exp2(poly)+bit-scale, rcp via Newton.
__device__ __forceinline__ float fast_silu(float x) {
    float t = x * -1.4426950408889634f;            // -x*log2(e)
    t = fminf(fmaxf(t, -126.0f), 126.0f);
    float s = __fadd_rn(t, 12582912.0f);           // round to nearest int
    int   sb = __float_as_int(s);
    float fi = __fadd_rn(s, -12582912.0f);
    float f  = t - fi;                             // [-0.5, 0.5]
    float p = 1.5404e-4f;
    p = fmaf(p, f, 1.3333558e-3f);
    p = fmaf(p, f, 9.6181291e-3f);
    p = fmaf(p, f, 5.5504109e-2f);
    p = fmaf(p, f, 2.4022651e-1f);
    p = fmaf(p, f, 6.9314718e-1f);
    p = fmaf(p, f, 1.0f);
    float scale = __int_as_float(0x3F800000 + ((sb - 0x4B400000) << 23)); // 2^i
    float e = p * scale;                           // exp(-x)
    float d = 1.0f + e;
    float r = __int_as_float(0x7EF311C3u - (uint32_t)__float_as_int(d));
    r = r * fmaf(-d, r, 2.0f);
    r = r * fmaf(-d, r, 2.0f);
    r = r * fmaf(-d, r, 2.0f);                     // 1/(1+exp(-x))
    return x * r;
}

// ---------------- mma.sync --------------------------------------------------
__device__ __forceinline__ void mma_bf16(float* d, const uint32_t* a, const uint32_t* b) {
    asm volatile(
        "mma.sync.aligned.m16n8k16.row.col.f32.bf16.bf16.f32 "
        "{%0,%1,%2,%3}, {%4,%5,%6,%7}, {%8,%9}, {%0,%1,%2,%3};"
        : "+f"(d[0]), "+f"(d[1]), "+f"(d[2]), "+f"(d[3])
        : "r"(a[0]), "r"(a[1]), "r"(a[2]), "r"(a[3]), "r"(b[0]), "r"(b[1]));
}

// Warp computes its 32x32 subtile of the 64x128 CTA tile (8 warps = 2x4 grid).
// A [64][KB] hi/lo and B [128][KB] hi/lo in smem, stride SA=KB+8 (bf16 units).
// 3-pass split: AhBh + AlBh + AhBl.
template <int KB, int SA>
__device__ __forceinline__ void warp_gemm(const char* sm, uint32_t oAh, uint32_t oAl,
                                          uint32_t oBh, uint32_t oBl,
                                          float (&acc)[2][4][4]) {
    const int lane = threadIdx.x & 31, w = threadIdx.x >> 5;
    const int wr = w >> 2, wc = w & 3;
    const int r4 = lane >> 2, kq = lane & 3;
    const int arow0 = wr * 32 + r4;
    const int bcol0 = wc * 32 + r4;
#pragma unroll
    for (int mi = 0; mi < 2; ++mi)
#pragma unroll
        for (int ni = 0; ni < 4; ++ni)
#pragma unroll
            for (int q = 0; q < 4; ++q) acc[mi][ni][q] = 0.f;

#pragma unroll
    for (int k0 = 0; k0 < KB; k0 += 16) {
        uint32_t ah[2][4], al[2][4], bh[4][2], bl[4][2];
#pragma unroll
        for (int mi = 0; mi < 2; ++mi) {
            int e = (arow0 + mi * 16) * SA + k0 + kq * 2;
            ah[mi][0] = *(const uint32_t*)(sm + oAh + 2 * e);
            ah[mi][1] = *(const uint32_t*)(sm + oAh + 2 * (e + 8 * SA));
            ah[mi][2] = *(const uint32_t*)(sm + oAh + 2 * (e + 8));
            ah[mi][3] = *(const uint32_t*)(sm + oAh + 2 * (e + 8 * SA + 8));
            al[mi][0] = *(const uint32_t*)(sm + oAl + 2 * e);
            al[mi][1] = *(const uint32_t*)(sm + oAl + 2 * (e + 8 * SA));
            al[mi][2] = *(const uint32_t*)(sm + oAl + 2 * (e + 8));
            al[mi][3] = *(const uint32_t*)(sm + oAl + 2 * (e + 8 * SA + 8));
        }
#pragma unroll
        for (int ni = 0; ni < 4; ++ni) {
            int e = (bcol0 + ni * 8) * SA + k0 + kq * 2;
            bh[ni][0] = *(const uint32_t*)(sm + oBh + 2 * e);
            bh[ni][1] = *(const uint32_t*)(sm + oBh + 2 * (e + 8));
            bl[ni][0] = *(const uint32_t*)(sm + oBl + 2 * e);
            bl[ni][1] = *(const uint32_t*)(sm + oBl + 2 * (e + 8));
        }
#pragma unroll
        for (int mi = 0; mi < 2; ++mi)
#pragma unroll
            for (int ni = 0; ni < 4; ++ni) mma_bf16(acc[mi][ni], ah[mi], bh[ni]);
#pragma unroll
        for (int mi = 0; mi < 2; ++mi)
#pragma unroll
            for (int ni = 0; ni < 4; ++ni) mma_bf16(acc[mi][ni], al[mi], bh[ni]);
#pragma unroll
        for (int mi = 0; mi < 2; ++mi)
#pragma unroll
            for (int ni = 0; ni < 4; ++ni) mma_bf16(acc[mi][ni], ah[mi], bl[ni]);
    }
}

__device__ __forceinline__ void acc_to_D(float* D, float (&acc)[2][4][4]) {
    const int lane = threadIdx.x & 31, w = threadIdx.x >> 5;
    const int wr = w >> 2, wc = w & 3;
    const int r4 = lane >> 2, kq = lane & 3;
#pragma unroll
    for (int mi = 0; mi < 2; ++mi) {
        int row = wr * 32 + mi * 16 + r4;
#pragma unroll
        for (int ni = 0; ni < 4; ++ni) {
            int col = wc * 32 + ni * 8 + kq * 2;
            *(float2*)&D[row * SD + col] = make_float2(acc[mi][ni][0], acc[mi][ni][1]);
            *(float2*)&D[(row + 8) * SD + col] = make_float2(acc[mi][ni][2], acc[mi][ni][3]);
        }
    }
}

// ---------------- fills / copies --------------------------------------------
__device__ __forceinline__ void split_store4(char* Ah, char* Al, int eoff, float4 v) {
    float h0, l0, h1, l1, h2, l2, h3, l3;
    sp(v.x, h0, l0); sp(v.y, h1, l1); sp(v.z, h2, l2); sp(v.w, h3, l3);
    *(uint2*)(Ah + 2 * eoff) = make_uint2(pk2(h0, h1), pk2(h2, h3));
    *(uint2*)(Al + 2 * eoff) = make_uint2(pk2(l0, l1), pk2(l2, l3));
}

__device__ __forceinline__ void fill_A128(char* Ah, char* Al,
                                          const float* __restrict__ src,
                                          long r0, int nrows) {
    for (int i = threadIdx.x; i < MT * 32; i += 256) {
        int r = i >> 5, c = (i & 31) * 4;
        float4 v = (r < nrows) ? *(const float4*)&src[(r0 + r) * H + c]
                               : make_float4(0.f, 0.f, 0.f, 0.f);
        split_store4(Ah, Al, r * SA128 + c, v);
    }
}

template <int KB>
__device__ __forceinline__ void copy_B(char* Bh, char* Bl,
                                       const __nv_bfloat16* __restrict__ sH,
                                       const __nv_bfloat16* __restrict__ sL) {
    const int SEG = KB / 8;
    for (int i = threadIdx.x; i < 128 * SEG; i += 256) {
        int r = i / SEG, s = i - r * SEG;
        *(uint4*)(Bh + (r * (KB + 8) + s * 8) * 2) = ((const uint4*)sH)[i];
        *(uint4*)(Bl + (r * (KB + 8) + s * 8) * 2) = ((const uint4*)sL)[i];
    }
}

// ---------------- small kernels ---------------------------------------------
__global__ void zero_m_kernel(size_t n4) {
    float4 z = make_float4(0.f, 0.f, 0.f, 0.f);
    for (size_t i = (size_t)blockIdx.x * blockDim.x + threadIdx.x; i < n4;
         i += (size_t)gridDim.x * blockDim.x)
        ((float4*)g_m)[i] = z;
}

__global__ void prep_kernel(const float* __restrict__ Wkj, const float* __restrict__ Wrbf2,
                            const float* __restrict__ Wdown, const float* __restrict__ Wsbf2,
                            const float* __restrict__ Wup, const float* __restrict__ Wr1a,
                            const float* __restrict__ Wr1b, const float* __restrict__ Wsbf1) {
    int idx = blockIdx.x * 256 + threadIdx.x;
    if (idx < 7 * 16384) {
        int mat = idx >> 14, rem = idx & 16383;
        int n = rem >> 7, k = rem & 127;
        const float* Ws[7] = {Wkj, Wrbf2, Wdown, Wsbf2, Wup, Wr1a, Wr1b};
        float v = Ws[mat][k * H + n];        // B[n][k] = W[k][n]
        float h, l; sp(v, h, l);
        g_WH[idx] = __float2bfloat16(h);
        g_WL[idx] = __float2bfloat16(l);
    } else {
        int rem = idx - 7 * 16384;
        if (rem < 8192) {
            int n = rem >> 6, k = rem & 63;
            float v = (k < 42) ? Wsbf1[k * H + n] : 0.f;
            float h, l; sp(v, h, l);
            g_W1H[rem] = __float2bfloat16(h);
            g_W1L[rem] = __float2bfloat16(l);
        }
    }
}

// ---------------- main kernels ----------------------------------------------
// epilogue thread mapping: row = tid>>2 (0..63), c0 = (tid&3)*32 (32 floats)

// K1: edge_down = silu((silu(x@Wkj+b)*silu(rbf@Wr2+b))@Wdown+b) -> split bf16
__global__ __launch_bounds__(256, 2)
void edge_kernel(const float* __restrict__ x, const float* __restrict__ rbf,
                 const float* __restrict__ b_kj, const float* __restrict__ b_rbf2,
                 const float* __restrict__ b_down, int E) {
    extern __shared__ __align__(16) char sm[];
    char* Ah = sm + OFF_AH; char* Al = sm + OFF_AL;
    char* Bh = sm + OFF_BH; char* Bl = sm + OFF_BL;
    float* D = (float*)(sm + OFF_D);
    const int tid = threadIdx.x;
    const int row = tid >> 2, c0 = (tid & 3) * 32;
    const long e0 = (long)blockIdx.x * MT;
    const int rows = (int)min((long)MT, (long)E - e0);
    float acc[2][4][4];
    float t1[32];

    // S0: x @ Wkj -> t1 = silu(.+b_kj)
    fill_A128(Ah, Al, x, e0, rows);
    copy_B<128>(Bh, Bl, g_WH + 0 * 16384, g_WL + 0 * 16384);
    __syncthreads();
    warp_gemm<128, SA128>(sm, OFF_AH, OFF_AL, OFF_BH, OFF_BL, acc);
    __syncthreads();
    acc_to_D(D, acc);
    __syncthreads();
#pragma unroll
    for (int g = 0; g < 8; ++g) {
        float4 d = *(const float4*)&D[row * SD + c0 + g * 4];
        float4 b = *(const float4*)&b_kj[c0 + g * 4];
        t1[g * 4 + 0] = fast_silu(d.x + b.x);
        t1[g * 4 + 1] = fast_silu(d.y + b.y);
        t1[g * 4 + 2] = fast_silu(d.z + b.z);
        t1[g * 4 + 3] = fast_silu(d.w + b.w);
    }
    __syncthreads();

    // S1: rbf @ Wrbf2 ; h = t1 * silu(.+b_rbf2) -> split into A
    fill_A128(Ah, Al, rbf, e0, rows);
    copy_B<128>(Bh, Bl, g_WH + 1 * 16384, g_WL + 1 * 16384);
    __syncthreads();
    warp_gemm<128, SA128>(sm, OFF_AH, OFF_AL, OFF_BH, OFF_BL, acc);
    __syncthreads();
    acc_to_D(D, acc);
    __syncthreads();
#pragma unroll
    for (int g = 0; g < 8; ++g) {
        float4 d = *(const float4*)&D[row * SD + c0 + g * 4];
        float4 b = *(const float4*)&b_rbf2[c0 + g * 4];
        float4 h;
        h.x = t1[g * 4 + 0] * fast_silu(d.x + b.x);
        h.y = t1[g * 4 + 1] * fast_silu(d.y + b.y);
        h.z = t1[g * 4 + 2] * fast_silu(d.z + b.z);
        h.w = t1[g * 4 + 3] * fast_silu(d.w + b.w);
        split_store4(Ah, Al, row * SA128 + c0 + g * 4, h);
    }
    __syncthreads();

    // S2: h @ Wdown -> silu(.+b_down) -> g_edge hi/lo
    copy_B<128>(Bh, Bl, g_WH + 2 * 16384, g_WL + 2 * 16384);
    __syncthreads();
    warp_gemm<128, SA128>(sm, OFF_AH, OFF_AL, OFF_BH, OFF_BL, acc);
    __syncthreads();
    acc_to_D(D, acc);
    __syncthreads();
    if (row < rows) {
        __nv_bfloat16* oh = g_edge_hi + (size_t)(e0 + row) * H + c0;
        __nv_bfloat16* ol = g_edge_lo + (size_t)(e0 + row) * H + c0;
#pragma unroll
        for (int g = 0; g < 8; ++g) {
            float4 d = *(const float4*)&D[row * SD + c0 + g * 4];
            float4 b = *(const float4*)&b_down[c0 + g * 4];
            float o0 = fast_silu(d.x + b.x), o1 = fast_silu(d.y + b.y);
            float o2 = fast_silu(d.z + b.z), o3 = fast_silu(d.w + b.w);
            float h0, l0, h1, l1, h2, l2, h3, l3;
            sp(o0, h0, l0); sp(o1, h1, l1); sp(o2, h2, l2); sp(o3, h3, l3);
            *(uint2*)(oh + g * 4) = make_uint2(pk2(h0, h1), pk2(h2, h3));
            *(uint2*)(ol + g * 4) = make_uint2(pk2(l0, l1), pk2(l2, l3));
        }
    }
}

// K2: s=silu(silu(sbf@W1)@W2); o=silu((edge[idx_kj]*s)@Wup+b); red.add -> g_m[idx_ji]
__global__ __launch_bounds__(256, 2)
void trip_kernel(const float* __restrict__ sbf, const int* __restrict__ idx_kj,
                 const int* __restrict__ idx_ji, const float* __restrict__ b_up, int T) {
    extern __shared__ __align__(16) char sm[];
    char* Ah = sm + OFF_AH; char* Al = sm + OFF_AL;
    char* Bh = sm + OFF_BH; char* Bl = sm + OFF_BL;
    float* D = (float*)(sm + OFF_D);
    int* skj = (int*)(sm + OFF_KJ);
    int* sji = (int*)(sm + OFF_JI);
    const int tid = threadIdx.x;
    const int row = tid >> 2, c0 = (tid & 3) * 32;
    const long t0 = (long)blockIdx.x * MT;
    const int rows = (int)min((long)MT, (long)T - t0);
    float acc[2][4][4];

    if (tid < MT) {
        long t = t0 + tid;
        skj[tid] = (tid < rows) ? idx_kj[t] : 0;
        sji[tid] = (tid < rows) ? idx_ji[t] : 0;
    }

    // S0: sbf @ Wsbf1 (K=64, cols 42..63 zero)
    for (int i = tid; i < MT * 64; i += 256) {
        int r = i >> 6, c = i & 63;
        float v = (c < 42 && r < rows) ? sbf[(t0 + r) * 42 + c] : 0.f;
        float h, l; sp(v, h, l);
        *(__nv_bfloat16*)(Ah + (r * SA64 + c) * 2) = __float2bfloat16(h);
        *(__nv_bfloat16*)(Al + (r * SA64 + c) * 2) = __float2bfloat16(l);
    }
    copy_B<64>(Bh, Bl, g_W1H, g_W1L);
    __syncthreads();
    warp_gemm<64, SA64>(sm, OFF_AH, OFF_AL, OFF_BH, OFF_BL, acc);
    __syncthreads();
    acc_to_D(D, acc);
    __syncthreads();
#pragma unroll
    for (int g = 0; g < 8; ++g) {
        float4 d = *(const float4*)&D[row * SD + c0 + g * 4];
        float4 o;
        o.x = fast_silu(d.x); o.y = fast_silu(d.y);
        o.z = fast_silu(d.z); o.w = fast_silu(d.w);
        split_store4(Ah, Al, row * SA128 + c0 + g * 4, o);
    }
    __syncthreads();

    // S1: @ Wsbf2 ; multiply gathered edge_down -> split into A
    copy_B<128>(Bh, Bl, g_WH + 3 * 16384, g_WL + 3 * 16384);
    __syncthreads();
    warp_gemm<128, SA128>(sm, OFF_AH, OFF_AL, OFF_BH, OFF_BL, acc);
    __syncthreads();
    acc_to_D(D, acc);
    __syncthreads();
    {
        size_t e = (size_t)skj[row];
        const __nv_bfloat16* gh = g_edge_hi + e * H + c0;
        const __nv_bfloat16* gl = g_edge_lo + e * H + c0;
#pragma unroll
        for (int g = 0; g < 8; ++g) {
            float4 d = *(const float4*)&D[row * SD + c0 + g * 4];
            uint2 uh = *(const uint2*)(gh + g * 4);
            uint2 ul = *(const uint2*)(gl + g * 4);
            __nv_bfloat162 h01 = *(__nv_bfloat162*)&uh.x;
            __nv_bfloat162 h23 = *(__nv_bfloat162*)&uh.y;
            __nv_bfloat162 l01 = *(__nv_bfloat162*)&ul.x;
            __nv_bfloat162 l23 = *(__nv_bfloat162*)&ul.y;
            float4 o;
            o.x = fast_silu(d.x) * (__bfloat162float(h01.x) + __bfloat162float(l01.x));
            o.y = fast_silu(d.y) * (__bfloat162float(h01.y) + __bfloat162float(l01.y));
            o.z = fast_silu(d.z) * (__bfloat162float(h23.x) + __bfloat162float(l23.x));
            o.w = fast_silu(d.w) * (__bfloat162float(h23.y) + __bfloat162float(l23.y));
            split_store4(Ah, Al, row * SA128 + c0 + g * 4, o);
        }
    }
    __syncthreads();

    // S2: @ Wup -> silu(.+b_up) -> scatter-add
    copy_B<128>(Bh, Bl, g_WH + 4 * 16384, g_WL + 4 * 16384);
    __syncthreads();
    warp_gemm<128, SA128>(sm, OFF_AH, OFF_AL, OFF_BH, OFF_BL, acc);
    __syncthreads();
    acc_to_D(D, acc);
    __syncthreads();
    if (row < rows) {
        float* mp = g_m + (size_t)sji[row] * H + c0;
#pragma unroll
        for (int g = 0; g < 8; ++g) {
            float4 d = *(const float4*)&D[row * SD + c0 + g * 4];
            float4 b = *(const float4*)&b_up[c0 + g * 4];
            float o0 = fast_silu(d.x + b.x), o1 = fast_silu(d.y + b.y);
            float o2 = fast_silu(d.z + b.z), o3 = fast_silu(d.w + b.w);
            asm volatile("red.global.add.v4.f32 [%0], {%1,%2,%3,%4};"
                         :: "l"(mp + g * 4), "f"(o0), "f"(o1), "f"(o2), "f"(o3)
                         : "memory");
        }
    }
}

// K3: out = m + silu(silu(m@Wr1a+b)@Wr1b+b) + x
__global__ __launch_bounds__(256, 2)
void res_kernel(const float* __restrict__ x, const float* __restrict__ b_r1a,
                const float* __restrict__ b_r1b, float* __restrict__ out, int E) {
    extern __shared__ __align__(16) char sm[];
    char* Ah = sm + OFF_AH; char* Al = sm + OFF_AL;
    char* Bh = sm + OFF_BH; char* Bl = sm + OFF_BL;
    float* D = (float*)(sm + OFF_D);
    const int tid = threadIdx.x;
    const int row = tid >> 2, c0 = (tid & 3) * 32;
    const long e0 = (long)blockIdx.x * MT;
    const int rows = (int)min((long)MT, (long)E - e0);
    float acc[2][4][4];

    // S0: m @ Wr1a
    fill_A128(Ah, Al, g_m, e0, rows);
    copy_B<128>(Bh, Bl, g_WH + 5 * 16384, g_WL + 5 * 16384);
    __syncthreads();
    warp_gemm<128, SA128>(sm, OFF_AH, OFF_AL, OFF_BH, OFF_BL, acc);
    __syncthreads();
    acc_to_D(D, acc);
    __syncthreads();
#pragma unroll
    for (int g = 0; g < 8; ++g) {
        float4 d = *(const float4*)&D[row * SD + c0 + g * 4];
        float4 b = *(const float4*)&b_r1a[c0 + g * 4];
        float4 o;
        o.x = fast_silu(d.x + b.x); o.y = fast_silu(d.y + b.y);
        o.z = fast_silu(d.z + b.z); o.w = fast_silu(d.w + b.w);
        split_store4(Ah, Al, row * SA128 + c0 + g * 4, o);
    }
    __syncthreads();

    // S1: @ Wr1b ; out = m + silu(.+b) + x
    copy_B<128>(Bh, Bl, g_WH + 6 * 16384, g_WL + 6 * 16384);
    __syncthreads();
    warp_gemm<128, SA128>(sm, OFF_AH, OFF_AL, OFF_BH, OFF_BL, acc);
    __syncthreads();
    acc_to_D(D, acc);
    __syncthreads();
    if (row < rows) {
        const float4* mp = (const float4*)(g_m + (size_t)(e0 + row) * H + c0);
        const float4* xp = (const float4*)(x + (size_t)(e0 + row) * H + c0);
        float4* op = (float4*)(out + (size_t)(e0 + row) * H + c0);
#pragma unroll
        for (int g = 0; g < 8; ++g) {
            float4 d = *(const float4*)&D[row * SD + c0 + g * 4];
            float4 b = *(const float4*)&b_r1b[c0 + g * 4];
            float4 mv = mp[g], xv = xp[g], o;
            o.x = mv.x + fast_silu(d.x + b.x) + xv.x;
            o.y = mv.y + fast_silu(d.y + b.y) + xv.y;
            o.z = mv.z + fast_silu(d.z + b.z) + xv.z;
            o.w = mv.w + fast_silu(d.w + b.w) + xv.w;
            op[g] = o;
        }
    }
}

// ---------------------------------------------------------------------------
extern "C" void kernel_launch(void* const* d_in, const int* in_sizes, int n_in,
                              void* d_out, int out_size) {
    const float* x      = (const float*)d_in[0];
    const float* rbf    = (const float*)d_in[1];
    const float* sbf    = (const float*)d_in[2];
    const int*   idx_kj = (const int*)d_in[3];
    const int*   idx_ji = (const int*)d_in[4];
    const float* W_rbf2 = (const float*)d_in[5];
    const float* b_rbf2 = (const float*)d_in[6];
    const float* W_sbf1 = (const float*)d_in[7];
    const float* W_sbf2 = (const float*)d_in[8];
    const float* W_kj   = (const float*)d_in[9];
    const float* b_kj   = (const float*)d_in[10];
    const float* W_down = (const float*)d_in[11];
    const float* b_down = (const float*)d_in[12];
    const float* W_up   = (const float*)d_in[13];
    const float* b_up   = (const float*)d_in[14];
    const float* W_r1a  = (const float*)d_in[15];
    const float* b_r1a  = (const float*)d_in[16];
    const float* W_r1b  = (const float*)d_in[17];
    const float* b_r1b  = (const float*)d_in[18];
    float* out = (float*)d_out;

    int E = in_sizes[0] / H;
    int T = in_sizes[3];

    cudaFuncSetAttribute(edge_kernel, cudaFuncAttributeMaxDynamicSharedMemorySize, SMEM_BYTES);
    cudaFuncSetAttribute(trip_kernel, cudaFuncAttributeMaxDynamicSharedMemorySize, SMEM_BYTES);
    cudaFuncSetAttribute(res_kernel, cudaFuncAttributeMaxDynamicSharedMemorySize, SMEM_BYTES);

    prep_kernel<<<480, 256>>>(W_kj, W_rbf2, W_down, W_sbf2, W_up, W_r1a, W_r1b, W_sbf1);
    zero_m_kernel<<<2048, 256>>>((size_t)E * H / 4);
    edge_kernel<<<(E + MT - 1) / MT, 256, SMEM_BYTES>>>(x, rbf, b_kj, b_rbf2, b_down, E);
    trip_kernel<<<(T + MT - 1) / MT, 256, SMEM_BYTES>>>(sbf, idx_kj, idx_ji, b_up, T);
    res_kernel<<<(E + MT - 1) / MT, 256, SMEM_BYTES>>>(x, b_r1a, b_r1b, out, E);
}

// round 6
// speedup vs baseline: 4.7809x; 1.0612x over previous
#include <cuda_runtime.h>
#include <cuda_bf16.h>
#include <cstdint>

#define H 128
#define MT 64              // rows per CTA tile (2 CTAs/SM)
#define MAX_E 250000

#define SA128 136          // bf16 stride for K=128 tiles
#define SA64  72           // bf16 stride for K=64 tiles
#define SD    132          // float stride for D buffer

// smem offsets (bytes). D overlays the A region (Ah+Al = 34816 >= 33792).
#define OFF_AH 0u
#define OFF_AL 17408u
#define OFF_BH 34816u
#define OFF_BL 69632u
#define OFF_D  0u
#define OFF_KJ 104448u
#define OFF_JI 104704u
#define SMEM_BYTES 105472

// ---------------- scratch ---------------------------------------------------
__device__ __align__(16) __nv_bfloat16 g_WH[7 * 16384];   // [mat][n][k] k=128
__device__ __align__(16) __nv_bfloat16 g_WL[7 * 16384];
__device__ __align__(16) __nv_bfloat16 g_W1H[8192];       // sbf1 [n][64]
__device__ __align__(16) __nv_bfloat16 g_W1L[8192];
__device__ __align__(16) __nv_bfloat16 g_edge_hi[(size_t)MAX_E * H];
__device__ __align__(16) __nv_bfloat16 g_edge_lo[(size_t)MAX_E * H];
__device__ __align__(16) float        g_m[(size_t)MAX_E * H];

// ---------------- helpers ---------------------------------------------------
__device__ __forceinline__ uint32_t smem_u32(const void* p) {
    uint32_t a;
    asm("{ .reg .u64 t; cvta.to.shared.u64 t, %1; cvt.u32.u64 %0, t; }"
        : "=r"(a) : "l"(p));
    return a;
}
__device__ __forceinline__ void sp(float v, float& h, float& l) {
    h = __bfloat162float(__float2bfloat16(v));
    l = v - h;
}
__device__ __forceinline__ uint32_t pk2(float a, float b) {
    __nv_bfloat162 t = __floats2bfloat162_rn(a, b);
    return *(uint32_t*)&t;
}

// MUFU-free silu: sigmoid via exp2(poly)+bit-scale, rcp via Newton.
__device__ __forceinline__ float fast_silu(float x) {
    float t = x * -1.4426950408889634f;
    t = fminf(fmaxf(t, -126.0f), 126.0f);
    float s = __fadd_rn(t, 12582912.0f);
    int   sb = __float_as_int(s);
    float fi = __fadd_rn(s, -12582912.0f);
    float f  = t - fi;
    float p = 1.5404e-4f;
    p = fmaf(p, f, 1.3333558e-3f);
    p = fmaf(p, f, 9.6181291e-3f);
    p = fmaf(p, f, 5.5504109e-2f);
    p = fmaf(p, f, 2.4022651e-1f);
    p = fmaf(p, f, 6.9314718e-1f);
    p = fmaf(p, f, 1.0f);
    float scale = __int_as_float(0x3F800000 + ((sb - 0x4B400000) << 23));
    float e = p * scale;
    float d = 1.0f + e;
    float r = __int_as_float(0x7EF311C3u - (uint32_t)__float_as_int(d));
    r = r * fmaf(-d, r, 2.0f);
    r = r * fmaf(-d, r, 2.0f);
    r = r * fmaf(-d, r, 2.0f);
    return x * r;
}

// ---------------- cp.async ---------------------------------------------------
__device__ __forceinline__ void cpa16(uint32_t dst, const void* src) {
    asm volatile("cp.async.cg.shared.global [%0], [%1], 16;" :: "r"(dst), "l"(src));
}
#define CP_COMMIT() asm volatile("cp.async.commit_group;" ::: "memory")
#define CP_WAIT0()  asm volatile("cp.async.wait_group 0;" ::: "memory")

template <int KB>
__device__ __forceinline__ void copyB_async(uint32_t Bh, uint32_t Bl,
                                            const __nv_bfloat16* __restrict__ sH,
                                            const __nv_bfloat16* __restrict__ sL) {
    const int SEG = KB / 8;
    for (int i = threadIdx.x; i < 128 * SEG; i += 256) {
        int r = i / SEG, s = i - r * SEG;
        uint32_t off = (uint32_t)((r * (KB + 8) + s * 8) * 2);
        cpa16(Bh + off, sH + i * 8);
        cpa16(Bl + off, sL + i * 8);
    }
    CP_COMMIT();
}

// ---------------- mma + ldmatrix --------------------------------------------
__device__ __forceinline__ void mma_bf16(float* d, const uint32_t* a, const uint32_t* b) {
    asm volatile(
        "mma.sync.aligned.m16n8k16.row.col.f32.bf16.bf16.f32 "
        "{%0,%1,%2,%3}, {%4,%5,%6,%7}, {%8,%9}, {%0,%1,%2,%3};"
        : "+f"(d[0]), "+f"(d[1]), "+f"(d[2]), "+f"(d[3])
        : "r"(a[0]), "r"(a[1]), "r"(a[2]), "r"(a[3]), "r"(b[0]), "r"(b[1]));
}
__device__ __forceinline__ void ldsm4(uint32_t* r, uint32_t addr) {
    asm volatile("ldmatrix.sync.aligned.m8n8.x4.shared.b16 {%0,%1,%2,%3}, [%4];"
                 : "=r"(r[0]), "=r"(r[1]), "=r"(r[2]), "=r"(r[3]) : "r"(addr));
}

// Warp computes its 32x32 subtile of the 64x128 CTA tile (8 warps = 2x4 grid).
// 3-pass split: AhBh + AlBh + AhBl. All fragments via ldmatrix.x4.
template <int KB, int SA>
__device__ __forceinline__ void warp_gemm(uint32_t sb, float (&acc)[2][4][4]) {
    const int lane = threadIdx.x & 31, w = threadIdx.x >> 5;
    const int wr = w >> 2, wc = w & 3;
    const int mrow = lane & 7, msel = lane >> 3;
    // A: matrices (row_off=(msel&1)*8, k_off=(msel>>1)*8)
    const uint32_t aoff0 = 2u * ((wr * 32 + (msel & 1) * 8 + mrow) * SA + (msel >> 1) * 8);
    const uint32_t aoff1 = aoff0 + 2u * 16 * SA;
    // B: matrices (n_off=(msel>>1)*8, k_off=(msel&1)*8); p selects 16-col group
    const uint32_t boff0 = 2u * ((wc * 32 + (msel >> 1) * 8 + mrow) * SA + (msel & 1) * 8);
    const uint32_t boff1 = boff0 + 2u * 16 * SA;

#pragma unroll
    for (int mi = 0; mi < 2; ++mi)
#pragma unroll
        for (int ni = 0; ni < 4; ++ni)
#pragma unroll
            for (int q = 0; q < 4; ++q) acc[mi][ni][q] = 0.f;

#pragma unroll
    for (int k0 = 0; k0 < KB; k0 += 16) {
        const uint32_t kb = 2u * k0;
        uint32_t ah[2][4], al[2][4], bh[2][4], bl[2][4];
        ldsm4(ah[0], sb + OFF_AH + aoff0 + kb);
        ldsm4(ah[1], sb + OFF_AH + aoff1 + kb);
        ldsm4(al[0], sb + OFF_AL + aoff0 + kb);
        ldsm4(al[1], sb + OFF_AL + aoff1 + kb);
        ldsm4(bh[0], sb + OFF_BH + boff0 + kb);
        ldsm4(bh[1], sb + OFF_BH + boff1 + kb);
        ldsm4(bl[0], sb + OFF_BL + boff0 + kb);
        ldsm4(bl[1], sb + OFF_BL + boff1 + kb);
#pragma unroll
        for (int mi = 0; mi < 2; ++mi)
#pragma unroll
            for (int p = 0; p < 2; ++p) {
                mma_bf16(acc[mi][2 * p + 0], ah[mi], &bh[p][0]);
                mma_bf16(acc[mi][2 * p + 1], ah[mi], &bh[p][2]);
            }
#pragma unroll
        for (int mi = 0; mi < 2; ++mi)
#pragma unroll
            for (int p = 0; p < 2; ++p) {
                mma_bf16(acc[mi][2 * p + 0], al[mi], &bh[p][0]);
                mma_bf16(acc[mi][2 * p + 1], al[mi], &bh[p][2]);
            }
#pragma unroll
        for (int mi = 0; mi < 2; ++mi)
#pragma unroll
            for (int p = 0; p < 2; ++p) {
                mma_bf16(acc[mi][2 * p + 0], ah[mi], &bl[p][0]);
                mma_bf16(acc[mi][2 * p + 1], ah[mi], &bl[p][2]);
            }
    }
}

__device__ __forceinline__ void acc_to_D(float* D, float (&acc)[2][4][4]) {
    const int lane = threadIdx.x & 31, w = threadIdx.x >> 5;
    const int wr = w >> 2, wc = w & 3;
    const int r4 = lane >> 2, kq = lane & 3;
#pragma unroll
    for (int mi = 0; mi < 2; ++mi) {
        int row = wr * 32 + mi * 16 + r4;
#pragma unroll
        for (int ni = 0; ni < 4; ++ni) {
            int col = wc * 32 + ni * 8 + kq * 2;
            *(float2*)&D[row * SD + col] = make_float2(acc[mi][ni][0], acc[mi][ni][1]);
            *(float2*)&D[(row + 8) * SD + col] = make_float2(acc[mi][ni][2], acc[mi][ni][3]);
        }
    }
}

// ---------------- fills ------------------------------------------------------
__device__ __forceinline__ void split_store4(char* Ah, char* Al, int eoff, float4 v) {
    float h0, l0, h1, l1, h2, l2, h3, l3;
    sp(v.x, h0, l0); sp(v.y, h1, l1); sp(v.z, h2, l2); sp(v.w, h3, l3);
    *(uint2*)(Ah + 2 * eoff) = make_uint2(pk2(h0, h1), pk2(h2, h3));
    *(uint2*)(Al + 2 * eoff) = make_uint2(pk2(l0, l1), pk2(l2, l3));
}

__device__ __forceinline__ void fill_A128(char* Ah, char* Al,
                                          const float* __restrict__ src,
                                          long r0, int nrows) {
    for (int i = threadIdx.x; i < MT * 32; i += 256) {
        int r = i >> 5, c = (i & 31) * 4;
        float4 v = (r < nrows) ? *(const float4*)&src[(r0 + r) * H + c]
                               : make_float4(0.f, 0.f, 0.f, 0.f);
        split_store4(Ah, Al, r * SA128 + c, v);
    }
}

// ---------------- small kernels ---------------------------------------------
__global__ void zero_m_kernel(size_t n4) {
    float4 z = make_float4(0.f, 0.f, 0.f, 0.f);
    for (size_t i = (size_t)blockIdx.x * blockDim.x + threadIdx.x; i < n4;
         i += (size_t)gridDim.x * blockDim.x)
        ((float4*)g_m)[i] = z;
}

__global__ void prep_kernel(const float* __restrict__ Wkj, const float* __restrict__ Wrbf2,
                            const float* __restrict__ Wdown, const float* __restrict__ Wsbf2,
                            const float* __restrict__ Wup, const float* __restrict__ Wr1a,
                            const float* __restrict__ Wr1b, const float* __restrict__ Wsbf1) {
    int idx = blockIdx.x * 256 + threadIdx.x;
    if (idx < 7 * 16384) {
        int mat = idx >> 14, rem = idx & 16383;
        int n = rem >> 7, k = rem & 127;
        const float* Ws[7] = {Wkj, Wrbf2, Wdown, Wsbf2, Wup, Wr1a, Wr1b};
        float v = Ws[mat][k * H + n];        // B[n][k] = W[k][n]
        float h, l; sp(v, h, l);
        g_WH[idx] = __float2bfloat16(h);
        g_WL[idx] = __float2bfloat16(l);
    } else {
        int rem = idx - 7 * 16384;
        if (rem < 8192) {
            int n = rem >> 6, k = rem & 63;
            float v = (k < 42) ? Wsbf1[k * H + n] : 0.f;
            float h, l; sp(v, h, l);
            g_W1H[rem] = __float2bfloat16(h);
            g_W1L[rem] = __float2bfloat16(l);
        }
    }
}

// ---------------- main kernels ----------------------------------------------
// epilogue mapping: row = tid>>2 (0..63), c0 = (tid&3)*32

// K1: edge_down = silu((silu(x@Wkj+b)*silu(rbf@Wr2+b))@Wdown+b) -> split bf16
__global__ __launch_bounds__(256, 2)
void edge_kernel(const float* __restrict__ x, const float* __restrict__ rbf,
                 const float* __restrict__ b_kj, const float* __restrict__ b_rbf2,
                 const float* __restrict__ b_down, int E) {
    extern __shared__ __align__(16) char sm[];
    uint32_t sb = smem_u32(sm);
    char* Ah = sm + OFF_AH; char* Al = sm + OFF_AL;
    float* D = (float*)(sm + OFF_D);
    const int tid = threadIdx.x;
    const int row = tid >> 2, c0 = (tid & 3) * 32;
    const long e0 = (long)blockIdx.x * MT;
    const int rows = (int)min((long)MT, (long)E - e0);
    float acc[2][4][4];
    float t1[32];

    // ---- S0: x @ Wkj
    copyB_async<128>(sb + OFF_BH, sb + OFF_BL, g_WH + 0 * 16384, g_WL + 0 * 16384);
    fill_A128(Ah, Al, x, e0, rows);
    CP_WAIT0(); __syncthreads();
    warp_gemm<128, SA128>(sb, acc);
    __syncthreads();
    copyB_async<128>(sb + OFF_BH, sb + OFF_BL, g_WH + 1 * 16384, g_WL + 1 * 16384);
    acc_to_D(D, acc);
    __syncthreads();
#pragma unroll
    for (int g = 0; g < 8; ++g) {
        float4 d = *(const float4*)&D[row * SD + c0 + g * 4];
        float4 b = *(const float4*)&b_kj[c0 + g * 4];
        t1[g * 4 + 0] = fast_silu(d.x + b.x);
        t1[g * 4 + 1] = fast_silu(d.y + b.y);
        t1[g * 4 + 2] = fast_silu(d.z + b.z);
        t1[g * 4 + 3] = fast_silu(d.w + b.w);
    }
    __syncthreads();                         // D reads done before A rewrite
    fill_A128(Ah, Al, rbf, e0, rows);
    CP_WAIT0(); __syncthreads();

    // ---- S1: rbf @ Wrbf2 ; h = t1 * silu(.)
    warp_gemm<128, SA128>(sb, acc);
    __syncthreads();
    copyB_async<128>(sb + OFF_BH, sb + OFF_BL, g_WH + 2 * 16384, g_WL + 2 * 16384);
    acc_to_D(D, acc);
    __syncthreads();
#pragma unroll
    for (int g = 0; g < 8; ++g) {
        float4 d = *(const float4*)&D[row * SD + c0 + g * 4];
        float4 b = *(const float4*)&b_rbf2[c0 + g * 4];
        t1[g * 4 + 0] *= fast_silu(d.x + b.x);
        t1[g * 4 + 1] *= fast_silu(d.y + b.y);
        t1[g * 4 + 2] *= fast_silu(d.z + b.z);
        t1[g * 4 + 3] *= fast_silu(d.w + b.w);
    }
    __syncthreads();
#pragma unroll
    for (int g = 0; g < 8; ++g)
        split_store4(Ah, Al, row * SA128 + c0 + g * 4,
                     make_float4(t1[g * 4], t1[g * 4 + 1], t1[g * 4 + 2], t1[g * 4 + 3]));
    CP_WAIT0(); __syncthreads();

    // ---- S2: h @ Wdown -> edge hi/lo
    warp_gemm<128, SA128>(sb, acc);
    __syncthreads();
    acc_to_D(D, acc);
    __syncthreads();
    if (row < rows) {
        __nv_bfloat16* oh = g_edge_hi + (size_t)(e0 + row) * H + c0;
        __nv_bfloat16* ol = g_edge_lo + (size_t)(e0 + row) * H + c0;
#pragma unroll
        for (int g = 0; g < 8; ++g) {
            float4 d = *(const float4*)&D[row * SD + c0 + g * 4];
            float4 b = *(const float4*)&b_down[c0 + g * 4];
            float o0 = fast_silu(d.x + b.x), o1 = fast_silu(d.y + b.y);
            float o2 = fast_silu(d.z + b.z), o3 = fast_silu(d.w + b.w);
            float h0, l0, h1, l1, h2, l2, h3, l3;
            sp(o0, h0, l0); sp(o1, h1, l1); sp(o2, h2, l2); sp(o3, h3, l3);
            *(uint2*)(oh + g * 4) = make_uint2(pk2(h0, h1), pk2(h2, h3));
            *(uint2*)(ol + g * 4) = make_uint2(pk2(l0, l1), pk2(l2, l3));
        }
    }
}

// K2: s=silu(silu(sbf@W1)@W2); o=silu((edge[idx_kj]*s)@Wup+b); red.add -> g_m[idx_ji]
__global__ __launch_bounds__(256, 2)
void trip_kernel(const float* __restrict__ sbf, const int* __restrict__ idx_kj,
                 const int* __restrict__ idx_ji, const float* __restrict__ b_up, int T) {
    extern __shared__ __align__(16) char sm[];
    uint32_t sb = smem_u32(sm);
    char* Ah = sm + OFF_AH; char* Al = sm + OFF_AL;
    float* D = (float*)(sm + OFF_D);
    int* skj = (int*)(sm + OFF_KJ);
    int* sji = (int*)(sm + OFF_JI);
    const int tid = threadIdx.x;
    const int row = tid >> 2, c0 = (tid & 3) * 32;
    const long t0 = (long)blockIdx.x * MT;
    const int rows = (int)min((long)MT, (long)T - t0);
    float acc[2][4][4];
    float v[32];

    if (tid < MT) {
        long t = t0 + tid;
        skj[tid] = (tid < rows) ? idx_kj[t] : 0;
        sji[tid] = (tid < rows) ? idx_ji[t] : 0;
    }

    // ---- S0: sbf @ Wsbf1 (K=64, cols 42..63 zero)
    copyB_async<64>(sb + OFF_BH, sb + OFF_BL, g_W1H, g_W1L);
    for (int i = tid; i < MT * 64; i += 256) {
        int r = i >> 6, c = i & 63;
        float val = (c < 42 && r < rows) ? sbf[(t0 + r) * 42 + c] : 0.f;
        float h, l; sp(val, h, l);
        *(__nv_bfloat16*)(Ah + (r * SA64 + c) * 2) = __float2bfloat16(h);
        *(__nv_bfloat16*)(Al + (r * SA64 + c) * 2) = __float2bfloat16(l);
    }
    CP_WAIT0(); __syncthreads();
    warp_gemm<64, SA64>(sb, acc);
    __syncthreads();
    copyB_async<128>(sb + OFF_BH, sb + OFF_BL, g_WH + 3 * 16384, g_WL + 3 * 16384);
    acc_to_D(D, acc);
    __syncthreads();
#pragma unroll
    for (int g = 0; g < 8; ++g) {
        float4 d = *(const float4*)&D[row * SD + c0 + g * 4];
        v[g * 4 + 0] = fast_silu(d.x); v[g * 4 + 1] = fast_silu(d.y);
        v[g * 4 + 2] = fast_silu(d.z); v[g * 4 + 3] = fast_silu(d.w);
    }
    __syncthreads();
#pragma unroll
    for (int g = 0; g < 8; ++g)
        split_store4(Ah, Al, row * SA128 + c0 + g * 4,
                     make_float4(v[g * 4], v[g * 4 + 1], v[g * 4 + 2], v[g * 4 + 3]));
    CP_WAIT0(); __syncthreads();

    // ---- S1: @ Wsbf2 ; multiply gathered edge_down
    warp_gemm<128, SA128>(sb, acc);
    __syncthreads();
    copyB_async<128>(sb + OFF_BH, sb + OFF_BL, g_WH + 4 * 16384, g_WL + 4 * 16384);
    acc_to_D(D, acc);
    __syncthreads();
    {
        size_t e = (size_t)skj[row];
        const __nv_bfloat16* gh = g_edge_hi + e * H + c0;
        const __nv_bfloat16* gl = g_edge_lo + e * H + c0;
#pragma unroll
        for (int g = 0; g < 8; ++g) {
            float4 d = *(const float4*)&D[row * SD + c0 + g * 4];
            uint2 uh = *(const uint2*)(gh + g * 4);
            uint2 ul = *(const uint2*)(gl + g * 4);
            __nv_bfloat162 h01 = *(__nv_bfloat162*)&uh.x;
            __nv_bfloat162 h23 = *(__nv_bfloat162*)&uh.y;
            __nv_bfloat162 l01 = *(__nv_bfloat162*)&ul.x;
            __nv_bfloat162 l23 = *(__nv_bfloat162*)&ul.y;
            v[g * 4 + 0] = fast_silu(d.x) * (__bfloat162float(h01.x) + __bfloat162float(l01.x));
            v[g * 4 + 1] = fast_silu(d.y) * (__bfloat162float(h01.y) + __bfloat162float(l01.y));
            v[g * 4 + 2] = fast_silu(d.z) * (__bfloat162float(h23.x) + __bfloat162float(l23.x));
            v[g * 4 + 3] = fast_silu(d.w) * (__bfloat162float(h23.y) + __bfloat162float(l23.y));
        }
    }
    __syncthreads();
#pragma unroll
    for (int g = 0; g < 8; ++g)
        split_store4(Ah, Al, row * SA128 + c0 + g * 4,
                     make_float4(v[g * 4], v[g * 4 + 1], v[g * 4 + 2], v[g * 4 + 3]));
    CP_WAIT0(); __syncthreads();

    // ---- S2: @ Wup -> silu(.+b_up) -> scatter-add
    warp_gemm<128, SA128>(sb, acc);
    __syncthreads();
    acc_to_D(D, acc);
    __syncthreads();
    if (row < rows) {
        float* mp = g_m + (size_t)sji[row] * H + c0;
#pragma unroll
        for (int g = 0; g < 8; ++g) {
            float4 d = *(const float4*)&D[row * SD + c0 + g * 4];
            float4 b = *(const float4*)&b_up[c0 + g * 4];
            float o0 = fast_silu(d.x + b.x), o1 = fast_silu(d.y + b.y);
            float o2 = fast_silu(d.z + b.z), o3 = fast_silu(d.w + b.w);
            asm volatile("red.global.add.v4.f32 [%0], {%1,%2,%3,%4};"
                         :: "l"(mp + g * 4), "f"(o0), "f"(o1), "f"(o2), "f"(o3)
                         : "memory");
        }
    }
}

// K3: out = m + silu(silu(m@Wr1a+b)@Wr1b+b) + x
__global__ __launch_bounds__(256, 2)
void res_kernel(const float* __restrict__ x, const float* __restrict__ b_r1a,
                const float* __restrict__ b_r1b, float* __restrict__ out, int E) {
    extern __shared__ __align__(16) char sm[];
    uint32_t sb = smem_u32(sm);
    char* Ah = sm + OFF_AH; char* Al = sm + OFF_AL;
    float* D = (float*)(sm + OFF_D);
    const int tid = threadIdx.x;
    const int row = tid >> 2, c0 = (tid & 3) * 32;
    const long e0 = (long)blockIdx.x * MT;
    const int rows = (int)min((long)MT, (long)E - e0);
    float acc[2][4][4];
    float v[32];

    // ---- S0: m @ Wr1a
    copyB_async<128>(sb + OFF_BH, sb + OFF_BL, g_WH + 5 * 16384, g_WL + 5 * 16384);
    fill_A128(Ah, Al, g_m, e0, rows);
    CP_WAIT0(); __syncthreads();
    warp_gemm<128, SA128>(sb, acc);
    __syncthreads();
    copyB_async<128>(sb + OFF_BH, sb + OFF_BL, g_WH + 6 * 16384, g_WL + 6 * 16384);
    acc_to_D(D, acc);
    __syncthreads();
#pragma unroll
    for (int g = 0; g < 8; ++g) {
        float4 d = *(const float4*)&D[row * SD + c0 + g * 4];
        float4 b = *(const float4*)&b_r1a[c0 + g * 4];
        v[g * 4 + 0] = fast_silu(d.x + b.x); v[g * 4 + 1] = fast_silu(d.y + b.y);
        v[g * 4 + 2] = fast_silu(d.z + b.z); v[g * 4 + 3] = fast_silu(d.w + b.w);
    }
    __syncthreads();
#pragma unroll
    for (int g = 0; g < 8; ++g)
        split_store4(Ah, Al, row * SA128 + c0 + g * 4,
                     make_float4(v[g * 4], v[g * 4 + 1], v[g * 4 + 2], v[g * 4 + 3]));
    CP_WAIT0(); __syncthreads();

    // ---- S1: @ Wr1b ; out = m + silu(.) + x
    warp_gemm<128, SA128>(sb, acc);
    __syncthreads();
    acc_to_D(D, acc);
    __syncthreads();
    if (row < rows) {
        const float4* mp = (const float4*)(g_m + (size_t)(e0 + row) * H + c0);
        const float4* xp = (const float4*)(x + (size_t)(e0 + row) * H + c0);
        float4* op = (float4*)(out + (size_t)(e0 + row) * H + c0);
#pragma unroll
        for (int g = 0; g < 8; ++g) {
            float4 d = *(const float4*)&D[row * SD + c0 + g * 4];
            float4 b = *(const float4*)&b_r1b[c0 + g * 4];
            float4 mv = mp[g], xv = xp[g], o;
            o.x = mv.x + fast_silu(d.x + b.x) + xv.x;
            o.y = mv.y + fast_silu(d.y + b.y) + xv.y;
            o.z = mv.z + fast_silu(d.z + b.z) + xv.z;
            o.w = mv.w + fast_silu(d.w + b.w) + xv.w;
            op[g] = o;
        }
    }
}

// ---------------------------------------------------------------------------
extern "C" void kernel_launch(void* const* d_in, const int* in_sizes, int n_in,
                              void* d_out, int out_size) {
    const float* x      = (const float*)d_in[0];
    const float* rbf    = (const float*)d_in[1];
    const float* sbf    = (const float*)d_in[2];
    const int*   idx_kj = (const int*)d_in[3];
    const int*   idx_ji = (const int*)d_in[4];
    const float* W_rbf2 = (const float*)d_in[5];
    const float* b_rbf2 = (const float*)d_in[6];
    const float* W_sbf1 = (const float*)d_in[7];
    const float* W_sbf2 = (const float*)d_in[8];
    const float* W_kj   = (const float*)d_in[9];
    const float* b_kj   = (const float*)d_in[10];
    const float* W_down = (const float*)d_in[11];
    const float* b_down = (const float*)d_in[12];
    const float* W_up   = (const float*)d_in[13];
    const float* b_up   = (const float*)d_in[14];
    const float* W_r1a  = (const float*)d_in[15];
    const float* b_r1a  = (const float*)d_in[16];
    const float* W_r1b  = (const float*)d_in[17];
    const float* b_r1b  = (const float*)d_in[18];
    float* out = (float*)d_out;

    int E = in_sizes[0] / H;
    int T = in_sizes[3];

    cudaFuncSetAttribute(edge_kernel, cudaFuncAttributeMaxDynamicSharedMemorySize, SMEM_BYTES);
    cudaFuncSetAttribute(trip_kernel, cudaFuncAttributeMaxDynamicSharedMemorySize, SMEM_BYTES);
    cudaFuncSetAttribute(res_kernel, cudaFuncAttributeMaxDynamicSharedMemorySize, SMEM_BYTES);

    prep_kernel<<<480, 256>>>(W_kj, W_rbf2, W_down, W_sbf2, W_up, W_r1a, W_r1b, W_sbf1);
    zero_m_kernel<<<2048, 256>>>((size_t)E * H / 4);
    edge_kernel<<<(E + MT - 1) / MT, 256, SMEM_BYTES>>>(x, rbf, b_kj, b_rbf2, b_down, E);
    trip_kernel<<<(T + MT - 1) / MT, 256, SMEM_BYTES>>>(sbf, idx_kj, idx_ji, b_up, T);
    res_kernel<<<(E + MT - 1) / MT, 256, SMEM_BYTES>>>(x, b_r1a, b_r1b, out, E);
}

// round 10
// speedup vs baseline: 5.2664x; 1.1016x over previous
#include <cuda_runtime.h>
#include <cuda_bf16.h>
#include <cstdint>

#define H 128
#define MT 64              // rows per CTA tile (2 CTAs/SM)
#define MAX_E 250000

#define SA128 136          // bf16 stride for K=128 tiles
#define SA64  72           // bf16 stride for K=64 tiles
#define SD    132          // float stride for D buffer (final stages only)

// smem offsets (bytes). D overlays the A region.
#define OFF_AH 0u
#define OFF_AL 17408u
#define OFF_BH 34816u
#define OFF_BL 69632u
#define OFF_D  0u
#define OFF_KJ 104448u
#define OFF_JI 104704u
#define SMEM_BYTES 105472

// ---------------- scratch ---------------------------------------------------
__device__ __align__(16) __nv_bfloat16 g_WH[7 * 16384];   // [mat][n][k] k=128
__device__ __align__(16) __nv_bfloat16 g_WL[7 * 16384];
__device__ __align__(16) __nv_bfloat16 g_W1H[8192];       // sbf1 [n][64]
__device__ __align__(16) __nv_bfloat16 g_W1L[8192];
__device__ __align__(16) __nv_bfloat16 g_edge_hi[(size_t)MAX_E * H];
__device__ __align__(16) __nv_bfloat16 g_edge_lo[(size_t)MAX_E * H];
__device__ __align__(16) float        g_m[(size_t)MAX_E * H];

// ---------------- helpers ---------------------------------------------------
__device__ __forceinline__ uint32_t smem_u32(const void* p) {
    uint32_t a;
    asm("{ .reg .u64 t; cvta.to.shared.u64 t, %1; cvt.u32.u64 %0, t; }"
        : "=r"(a) : "l"(p));
    return a;
}
__device__ __forceinline__ void sp(float v, float& h, float& l) {
    h = __bfloat162float(__float2bfloat16(v));
    l = v - h;
}
__device__ __forceinline__ uint32_t pk2(float a, float b) {
    __nv_bfloat162 t = __floats2bfloat162_rn(a, b);
    return *(uint32_t*)&t;
}
__device__ __forceinline__ void prefetchL2(const void* p) {
    asm volatile("prefetch.global.L2 [%0];" :: "l"(p));
}

// MUFU-free silu: sigmoid via exp2(poly)+bit-scale, rcp via Newton.
__device__ __forceinline__ float fast_silu(float x) {
    float t = x * -1.4426950408889634f;
    t = fminf(fmaxf(t, -126.0f), 126.0f);
    float s = __fadd_rn(t, 12582912.0f);
    int   sb = __float_as_int(s);
    float fi = __fadd_rn(s, -12582912.0f);
    float f  = t - fi;
    float p = 1.5404e-4f;
    p = fmaf(p, f, 1.3333558e-3f);
    p = fmaf(p, f, 9.6181291e-3f);
    p = fmaf(p, f, 5.5504109e-2f);
    p = fmaf(p, f, 2.4022651e-1f);
    p = fmaf(p, f, 6.9314718e-1f);
    p = fmaf(p, f, 1.0f);
    float scale = __int_as_float(0x3F800000 + ((sb - 0x4B400000) << 23));
    float e = p * scale;
    float d = 1.0f + e;
    float r = __int_as_float(0x7EF311C3u - (uint32_t)__float_as_int(d));
    r = r * fmaf(-d, r, 2.0f);
    r = r * fmaf(-d, r, 2.0f);
    r = r * fmaf(-d, r, 2.0f);
    return x * r;
}

// ---------------- cp.async ---------------------------------------------------
__device__ __forceinline__ void cpa16(uint32_t dst, const void* src) {
    asm volatile("cp.async.cg.shared.global [%0], [%1], 16;" :: "r"(dst), "l"(src));
}
#define CP_COMMIT() asm volatile("cp.async.commit_group;" ::: "memory")
#define CP_WAIT0()  asm volatile("cp.async.wait_group 0;" ::: "memory")

template <int KB>
__device__ __forceinline__ void copyB_async(uint32_t Bh, uint32_t Bl,
                                            const __nv_bfloat16* __restrict__ sH,
                                            const __nv_bfloat16* __restrict__ sL) {
    const int SEG = KB / 8;
    for (int i = threadIdx.x; i < 128 * SEG; i += 256) {
        int r = i / SEG, s = i - r * SEG;
        uint32_t off = (uint32_t)((r * (KB + 8) + s * 8) * 2);
        cpa16(Bh + off, sH + i * 8);
        cpa16(Bl + off, sL + i * 8);
    }
    CP_COMMIT();
}

// ---------------- mma + ldmatrix --------------------------------------------
__device__ __forceinline__ void mma_bf16(float* d, const uint32_t* a, const uint32_t* b) {
    asm volatile(
        "mma.sync.aligned.m16n8k16.row.col.f32.bf16.bf16.f32 "
        "{%0,%1,%2,%3}, {%4,%5,%6,%7}, {%8,%9}, {%0,%1,%2,%3};"
        : "+f"(d[0]), "+f"(d[1]), "+f"(d[2]), "+f"(d[3])
        : "r"(a[0]), "r"(a[1]), "r"(a[2]), "r"(a[3]), "r"(b[0]), "r"(b[1]));
}
__device__ __forceinline__ void ldsm4(uint32_t* r, uint32_t addr) {
    asm volatile("ldmatrix.sync.aligned.m8n8.x4.shared.b16 {%0,%1,%2,%3}, [%4];"
                 : "=r"(r[0]), "=r"(r[1]), "=r"(r[2]), "=r"(r[3]) : "r"(addr));
}

// Warp computes its 32x32 subtile of the 64x128 CTA tile (8 warps = 2x4 grid).
// 3-pass split: AhBh + AlBh + AhBl. All fragments via ldmatrix.x4.
template <int KB, int SA>
__device__ __forceinline__ void warp_gemm(uint32_t sb, float (&acc)[2][4][4]) {
    const int lane = threadIdx.x & 31, w = threadIdx.x >> 5;
    const int wr = w >> 2, wc = w & 3;
    const int mrow = lane & 7, msel = lane >> 3;
    const uint32_t aoff0 = 2u * ((wr * 32 + (msel & 1) * 8 + mrow) * SA + (msel >> 1) * 8);
    const uint32_t aoff1 = aoff0 + 2u * 16 * SA;
    const uint32_t boff0 = 2u * ((wc * 32 + (msel >> 1) * 8 + mrow) * SA + (msel & 1) * 8);
    const uint32_t boff1 = boff0 + 2u * 16 * SA;

#pragma unroll
    for (int mi = 0; mi < 2; ++mi)
#pragma unroll
        for (int ni = 0; ni < 4; ++ni)
#pragma unroll
            for (int q = 0; q < 4; ++q) acc[mi][ni][q] = 0.f;

#pragma unroll
    for (int k0 = 0; k0 < KB; k0 += 16) {
        const uint32_t kb = 2u * k0;
        uint32_t ah[2][4], al[2][4], bh[2][4], bl[2][4];
        ldsm4(ah[0], sb + OFF_AH + aoff0 + kb);
        ldsm4(ah[1], sb + OFF_AH + aoff1 + kb);
        ldsm4(al[0], sb + OFF_AL + aoff0 + kb);
        ldsm4(al[1], sb + OFF_AL + aoff1 + kb);
        ldsm4(bh[0], sb + OFF_BH + boff0 + kb);
        ldsm4(bh[1], sb + OFF_BH + boff1 + kb);
        ldsm4(bl[0], sb + OFF_BL + boff0 + kb);
        ldsm4(bl[1], sb + OFF_BL + boff1 + kb);
#pragma unroll
        for (int mi = 0; mi < 2; ++mi)
#pragma unroll
            for (int p = 0; p < 2; ++p) {
                mma_bf16(acc[mi][2 * p + 0], ah[mi], &bh[p][0]);
                mma_bf16(acc[mi][2 * p + 1], ah[mi], &bh[p][2]);
            }
#pragma unroll
        for (int mi = 0; mi < 2; ++mi)
#pragma unroll
            for (int p = 0; p < 2; ++p) {
                mma_bf16(acc[mi][2 * p + 0], al[mi], &bh[p][0]);
                mma_bf16(acc[mi][2 * p + 1], al[mi], &bh[p][2]);
            }
#pragma unroll
        for (int mi = 0; mi < 2; ++mi)
#pragma unroll
            for (int p = 0; p < 2; ++p) {
                mma_bf16(acc[mi][2 * p + 0], ah[mi], &bl[p][0]);
                mma_bf16(acc[mi][2 * p + 1], ah[mi], &bl[p][2]);
            }
    }
}

__device__ __forceinline__ void acc_to_D(float* D, float (&acc)[2][4][4]) {
    const int lane = threadIdx.x & 31, w = threadIdx.x >> 5;
    const int wr = w >> 2, wc = w & 3;
    const int r4 = lane >> 2, kq = lane & 3;
#pragma unroll
    for (int mi = 0; mi < 2; ++mi) {
        int row = wr * 32 + mi * 16 + r4;
#pragma unroll
        for (int ni = 0; ni < 4; ++ni) {
            int col = wc * 32 + ni * 8 + kq * 2;
            *(float2*)&D[row * SD + col] = make_float2(acc[mi][ni][0], acc[mi][ni][1]);
            *(float2*)&D[(row + 8) * SD + col] = make_float2(acc[mi][ni][2], acc[mi][ni][3]);
        }
    }
}

// Store fragment (split hi/lo) directly into A-smem in SA128 layout.
__device__ __forceinline__ void frag_store_split(char* Ah, char* Al,
                                                 const float (&a)[2][4][4],
                                                 int wr, int wc, int qr, int kq) {
#pragma unroll
    for (int mi = 0; mi < 2; ++mi)
#pragma unroll
        for (int h2 = 0; h2 < 2; ++h2) {
            int row = wr * 32 + mi * 16 + h2 * 8 + qr;
#pragma unroll
            for (int ni = 0; ni < 4; ++ni) {
                int col = wc * 32 + ni * 8 + kq * 2;
                float v0 = a[mi][ni][h2 * 2 + 0], v1 = a[mi][ni][h2 * 2 + 1];
                float h0, l0, h1, l1;
                sp(v0, h0, l0); sp(v1, h1, l1);
                uint32_t off = 2u * (row * SA128 + col);
                *(uint32_t*)(Ah + off) = pk2(h0, h1);
                *(uint32_t*)(Al + off) = pk2(l0, l1);
            }
        }
}

// Load per-thread fragment bias: bias[ni] = {b[col], b[col+1]}.
__device__ __forceinline__ void bias_frag(const float* __restrict__ b,
                                          int wc, int kq, float2 (&o)[4]) {
#pragma unroll
    for (int ni = 0; ni < 4; ++ni)
        o[ni] = *(const float2*)&b[wc * 32 + ni * 8 + kq * 2];
}

// ---------------- fills ------------------------------------------------------
__device__ __forceinline__ void split_store4(char* Ah, char* Al, int eoff, float4 v) {
    float h0, l0, h1, l1, h2, l2, h3, l3;
    sp(v.x, h0, l0); sp(v.y, h1, l1); sp(v.z, h2, l2); sp(v.w, h3, l3);
    *(uint2*)(Ah + 2 * eoff) = make_uint2(pk2(h0, h1), pk2(h2, h3));
    *(uint2*)(Al + 2 * eoff) = make_uint2(pk2(l0, l1), pk2(l2, l3));
}

__device__ __forceinline__ void fill_A128(char* Ah, char* Al,
                                          const float* __restrict__ src,
                                          long r0, int nrows) {
    for (int i = threadIdx.x; i < MT * 32; i += 256) {
        int r = i >> 5, c = (i & 31) * 4;
        float4 v = (r < nrows) ? *(const float4*)&src[(r0 + r) * H + c]
                               : make_float4(0.f, 0.f, 0.f, 0.f);
        split_store4(Ah, Al, r * SA128 + c, v);
    }
}

// ---------------- small kernels ---------------------------------------------
__global__ void zero_m_kernel(size_t n4) {
    float4 z = make_float4(0.f, 0.f, 0.f, 0.f);
    for (size_t i = (size_t)blockIdx.x * blockDim.x + threadIdx.x; i < n4;
         i += (size_t)gridDim.x * blockDim.x)
        ((float4*)g_m)[i] = z;
}

__global__ void prep_kernel(const float* __restrict__ Wkj, const float* __restrict__ Wrbf2,
                            const float* __restrict__ Wdown, const float* __restrict__ Wsbf2,
                            const float* __restrict__ Wup, const float* __restrict__ Wr1a,
                            const float* __restrict__ Wr1b, const float* __restrict__ Wsbf1) {
    int idx = blockIdx.x * 256 + threadIdx.x;
    if (idx < 7 * 16384) {
        int mat = idx >> 14, rem = idx & 16383;
        int n = rem >> 7, k = rem & 127;
        const float* Ws[7] = {Wkj, Wrbf2, Wdown, Wsbf2, Wup, Wr1a, Wr1b};
        float v = Ws[mat][k * H + n];        // B[n][k] = W[k][n]
        float h, l; sp(v, h, l);
        g_WH[idx] = __float2bfloat16(h);
        g_WL[idx] = __float2bfloat16(l);
    } else {
        int rem = idx - 7 * 16384;
        if (rem < 8192) {
            int n = rem >> 6, k = rem & 63;
            float v = (k < 42) ? Wsbf1[k * H + n] : 0.f;
            float h, l; sp(v, h, l);
            g_W1H[rem] = __float2bfloat16(h);
            g_W1L[rem] = __float2bfloat16(l);
        }
    }
}

// ---------------- main kernels ----------------------------------------------
// K1: edge_down = silu((silu(x@Wkj+b)*silu(rbf@Wr2+b))@Wdown+b) -> split bf16
__global__ __launch_bounds__(256, 2)
void edge_kernel(const float* __restrict__ x, const float* __restrict__ rbf,
                 const float* __restrict__ b_kj, const float* __restrict__ b_rbf2,
                 const float* __restrict__ b_down, int E) {
    extern __shared__ __align__(16) char sm[];
    uint32_t sb = smem_u32(sm);
    char* Ah = sm + OFF_AH; char* Al = sm + OFF_AL;
    float* D = (float*)(sm + OFF_D);
    const int tid = threadIdx.x, lane = tid & 31, w = tid >> 5;
    const int wr = w >> 2, wc = w & 3, qr = lane >> 2, kq = lane & 3;
    const long e0 = (long)blockIdx.x * MT;
    const int rows = (int)min((long)MT, (long)E - e0);
    float acc[2][4][4], t1[2][4][4];

    // ---- S0: x @ Wkj -> t1 = silu(.+b) (fragment-resident)
    copyB_async<128>(sb + OFF_BH, sb + OFF_BL, g_WH + 0 * 16384, g_WL + 0 * 16384);
    fill_A128(Ah, Al, x, e0, rows);
    CP_WAIT0(); __syncthreads();
    warp_gemm<128, SA128>(sb, acc);
    __syncthreads();
    copyB_async<128>(sb + OFF_BH, sb + OFF_BL, g_WH + 1 * 16384, g_WL + 1 * 16384);
    {
        float2 b2[4]; bias_frag(b_kj, wc, kq, b2);
#pragma unroll
        for (int mi = 0; mi < 2; ++mi)
#pragma unroll
            for (int ni = 0; ni < 4; ++ni) {
                t1[mi][ni][0] = fast_silu(acc[mi][ni][0] + b2[ni].x);
                t1[mi][ni][1] = fast_silu(acc[mi][ni][1] + b2[ni].y);
                t1[mi][ni][2] = fast_silu(acc[mi][ni][2] + b2[ni].x);
                t1[mi][ni][3] = fast_silu(acc[mi][ni][3] + b2[ni].y);
            }
    }
    fill_A128(Ah, Al, rbf, e0, rows);
    CP_WAIT0(); __syncthreads();

    // ---- S1: rbf @ Wrbf2 ; h = t1 * silu(.) -> frag store to A
    warp_gemm<128, SA128>(sb, acc);
    __syncthreads();
    copyB_async<128>(sb + OFF_BH, sb + OFF_BL, g_WH + 2 * 16384, g_WL + 2 * 16384);
    {
        float2 b2[4]; bias_frag(b_rbf2, wc, kq, b2);
#pragma unroll
        for (int mi = 0; mi < 2; ++mi)
#pragma unroll
            for (int ni = 0; ni < 4; ++ni) {
                acc[mi][ni][0] = t1[mi][ni][0] * fast_silu(acc[mi][ni][0] + b2[ni].x);
                acc[mi][ni][1] = t1[mi][ni][1] * fast_silu(acc[mi][ni][1] + b2[ni].y);
                acc[mi][ni][2] = t1[mi][ni][2] * fast_silu(acc[mi][ni][2] + b2[ni].x);
                acc[mi][ni][3] = t1[mi][ni][3] * fast_silu(acc[mi][ni][3] + b2[ni].y);
            }
    }
    frag_store_split(Ah, Al, acc, wr, wc, qr, kq);
    CP_WAIT0(); __syncthreads();

    // ---- S2: h @ Wdown -> edge hi/lo (D round-trip for coalesced store)
    warp_gemm<128, SA128>(sb, acc);
    __syncthreads();
    acc_to_D(D, acc);
    __syncthreads();
    {
        const int row = tid >> 2, c0 = (tid & 3) * 32;
        if (row < rows) {
            __nv_bfloat16* oh = g_edge_hi + (size_t)(e0 + row) * H + c0;
            __nv_bfloat16* ol = g_edge_lo + (size_t)(e0 + row) * H + c0;
#pragma unroll
            for (int g = 0; g < 8; ++g) {
                float4 d = *(const float4*)&D[row * SD + c0 + g * 4];
                float4 b = *(const float4*)&b_down[c0 + g * 4];
                float o0 = fast_silu(d.x + b.x), o1 = fast_silu(d.y + b.y);
                float o2 = fast_silu(d.z + b.z), o3 = fast_silu(d.w + b.w);
                float h0, l0, h1, l1, h2, l2, h3, l3;
                sp(o0, h0, l0); sp(o1, h1, l1); sp(o2, h2, l2); sp(o3, h3, l3);
                *(uint2*)(oh + g * 4) = make_uint2(pk2(h0, h1), pk2(h2, h3));
                *(uint2*)(ol + g * 4) = make_uint2(pk2(l0, l1), pk2(l2, l3));
            }
        }
    }
}

// K2: s=silu(silu(sbf@W1)@W2); o=silu((edge[idx_kj]*s)@Wup+b); red.add -> g_m[idx_ji]
__global__ __launch_bounds__(256, 2)
void trip_kernel(const float* __restrict__ sbf, const int* __restrict__ idx_kj,
                 const int* __restrict__ idx_ji, const float* __restrict__ b_up, int T) {
    extern __shared__ __align__(16) char sm[];
    uint32_t sb = smem_u32(sm);
    char* Ah = sm + OFF_AH; char* Al = sm + OFF_AL;
    float* D = (float*)(sm + OFF_D);
    int* skj = (int*)(sm + OFF_KJ);
    int* sji = (int*)(sm + OFF_JI);
    const int tid = threadIdx.x, lane = tid & 31, w = tid >> 5;
    const int wr = w >> 2, wc = w & 3, qr = lane >> 2, kq = lane & 3;
    const long t0 = (long)blockIdx.x * MT;
    const int rows = (int)min((long)MT, (long)T - t0);
    float acc[2][4][4];

    if (tid < MT) {
        long t = t0 + tid;
        skj[tid] = (tid < rows) ? idx_kj[t] : 0;
        sji[tid] = (tid < rows) ? idx_ji[t] : 0;
    }

    // ---- S0: sbf @ Wsbf1 (K=64, cols 42..63 zero)
    copyB_async<64>(sb + OFF_BH, sb + OFF_BL, g_W1H, g_W1L);
    for (int i = tid; i < MT * 64; i += 256) {
        int r = i >> 6, c = i & 63;
        float val = (c < 42 && r < rows) ? sbf[(t0 + r) * 42 + c] : 0.f;
        float h, l; sp(val, h, l);
        *(__nv_bfloat16*)(Ah + (r * SA64 + c) * 2) = __float2bfloat16(h);
        *(__nv_bfloat16*)(Al + (r * SA64 + c) * 2) = __float2bfloat16(l);
    }
    CP_WAIT0(); __syncthreads();
    warp_gemm<64, SA64>(sb, acc);
    __syncthreads();
    copyB_async<128>(sb + OFF_BH, sb + OFF_BL, g_WH + 3 * 16384, g_WL + 3 * 16384);
#pragma unroll
    for (int mi = 0; mi < 2; ++mi)
#pragma unroll
        for (int ni = 0; ni < 4; ++ni)
#pragma unroll
            for (int q = 0; q < 4; ++q) acc[mi][ni][q] = fast_silu(acc[mi][ni][q]);
    frag_store_split(Ah, Al, acc, wr, wc, qr, kq);
    // Prefetch the gather rows for S1 epilogue (hides DRAM latency under S1 gemm)
#pragma unroll
    for (int mi = 0; mi < 2; ++mi)
#pragma unroll
        for (int h2 = 0; h2 < 2; ++h2) {
            int row = wr * 32 + mi * 16 + h2 * 8 + qr;
            size_t e = (size_t)skj[row];
            prefetchL2(g_edge_hi + e * H + wc * 32);
            prefetchL2(g_edge_lo + e * H + wc * 32);
        }
    CP_WAIT0(); __syncthreads();

    // ---- S1: @ Wsbf2 ; multiply gathered edge_down (fragment gather)
    warp_gemm<128, SA128>(sb, acc);
    __syncthreads();
    copyB_async<128>(sb + OFF_BH, sb + OFF_BL, g_WH + 4 * 16384, g_WL + 4 * 16384);
#pragma unroll
    for (int mi = 0; mi < 2; ++mi)
#pragma unroll
        for (int h2 = 0; h2 < 2; ++h2) {
            int row = wr * 32 + mi * 16 + h2 * 8 + qr;
            size_t e = (size_t)skj[row];
            const char* ph = (const char*)(g_edge_hi + e * H + wc * 32 + kq * 2);
            const char* pl = (const char*)(g_edge_lo + e * H + wc * 32 + kq * 2);
#pragma unroll
            for (int ni = 0; ni < 4; ++ni) {
                uint32_t uh = *(const uint32_t*)(ph + ni * 16);
                uint32_t ul = *(const uint32_t*)(pl + ni * 16);
                __nv_bfloat162 hh = *(__nv_bfloat162*)&uh;
                __nv_bfloat162 ll = *(__nv_bfloat162*)&ul;
                acc[mi][ni][h2 * 2 + 0] = fast_silu(acc[mi][ni][h2 * 2 + 0]) *
                    (__bfloat162float(hh.x) + __bfloat162float(ll.x));
                acc[mi][ni][h2 * 2 + 1] = fast_silu(acc[mi][ni][h2 * 2 + 1]) *
                    (__bfloat162float(hh.y) + __bfloat162float(ll.y));
            }
        }
    frag_store_split(Ah, Al, acc, wr, wc, qr, kq);
    CP_WAIT0(); __syncthreads();

    // ---- S2: @ Wup -> silu(.+b_up) -> scatter-add (D round-trip for red.v4)
    warp_gemm<128, SA128>(sb, acc);
    __syncthreads();
    acc_to_D(D, acc);
    __syncthreads();
    {
        const int row = tid >> 2, c0 = (tid & 3) * 32;
        if (row < rows) {
            float* mp = g_m + (size_t)sji[row] * H + c0;
#pragma unroll
            for (int g = 0; g < 8; ++g) {
                float4 d = *(const float4*)&D[row * SD + c0 + g * 4];
                float4 b = *(const float4*)&b_up[c0 + g * 4];
                float o0 = fast_silu(d.x + b.x), o1 = fast_silu(d.y + b.y);
                float o2 = fast_silu(d.z + b.z), o3 = fast_silu(d.w + b.w);
                asm volatile("red.global.add.v4.f32 [%0], {%1,%2,%3,%4};"
                             :: "l"(mp + g * 4), "f"(o0), "f"(o1), "f"(o2), "f"(o3)
                             : "memory");
            }
        }
    }
}

// K3: out = m + silu(silu(m@Wr1a+b)@Wr1b+b) + x
__global__ __launch_bounds__(256, 2)
void res_kernel(const float* __restrict__ x, const float* __restrict__ b_r1a,
                const float* __restrict__ b_r1b, float* __restrict__ out, int E) {
    extern __shared__ __align__(16) char sm[];
    uint32_t sb = smem_u32(sm);
    char* Ah = sm + OFF_AH; char* Al = sm + OFF_AL;
    float* D = (float*)(sm + OFF_D);
    const int tid = threadIdx.x, lane = tid & 31, w = tid >> 5;
    const int wr = w >> 2, wc = w & 3, qr = lane >> 2, kq = lane & 3;
    const long e0 = (long)blockIdx.x * MT;
    const int rows = (int)min((long)MT, (long)E - e0);
    float acc[2][4][4];

    // ---- S0: m @ Wr1a -> silu -> frag store
    copyB_async<128>(sb + OFF_BH, sb + OFF_BL, g_WH + 5 * 16384, g_WL + 5 * 16384);
    fill_A128(Ah, Al, g_m, e0, rows);
    CP_WAIT0(); __syncthreads();
    warp_gemm<128, SA128>(sb, acc);
    __syncthreads();
    copyB_async<128>(sb + OFF_BH, sb + OFF_BL, g_WH + 6 * 16384, g_WL + 6 * 16384);
    {
        float2 b2[4]; bias_frag(b_r1a, wc, kq, b2);
#pragma unroll
        for (int mi = 0; mi < 2; ++mi)
#pragma unroll
            for (int ni = 0; ni < 4; ++ni) {
                acc[mi][ni][0] = fast_silu(acc[mi][ni][0] + b2[ni].x);
                acc[mi][ni][1] = fast_silu(acc[mi][ni][1] + b2[ni].y);
                acc[mi][ni][2] = fast_silu(acc[mi][ni][2] + b2[ni].x);
                acc[mi][ni][3] = fast_silu(acc[mi][ni][3] + b2[ni].y);
            }
    }
    frag_store_split(Ah, Al, acc, wr, wc, qr, kq);
    CP_WAIT0(); __syncthreads();

    // ---- S1: @ Wr1b ; out = m + silu(.) + x (D round-trip for coalesced IO)
    warp_gemm<128, SA128>(sb, acc);
    __syncthreads();
    acc_to_D(D, acc);
    __syncthreads();
    {
        const int row = tid >> 2, c0 = (tid & 3) * 32;
        if (row < rows) {
            const float4* mp = (const float4*)(g_m + (size_t)(e0 + row) * H + c0);
            const float4* xp = (const float4*)(x + (size_t)(e0 + row) * H + c0);
            float4* op = (float4*)(out + (size_t)(e0 + row) * H + c0);
#pragma unroll
            for (int g = 0; g < 8; ++g) {
                float4 d = *(const float4*)&D[row * SD + c0 + g * 4];
                float4 b = *(const float4*)&b_r1b[c0 + g * 4];
                float4 mv = mp[g], xv = xp[g], o;
                o.x = mv.x + fast_silu(d.x + b.x) + xv.x;
                o.y = mv.y + fast_silu(d.y + b.y) + xv.y;
                o.z = mv.z + fast_silu(d.z + b.z) + xv.z;
                o.w = mv.w + fast_silu(d.w + b.w) + xv.w;
                op[g] = o;
            }
        }
    }
}

// ---------------------------------------------------------------------------
extern "C" void kernel_launch(void* const* d_in, const int* in_sizes, int n_in,
                              void* d_out, int out_size) {
    const float* x      = (const float*)d_in[0];
    const float* rbf    = (const float*)d_in[1];
    const float* sbf    = (const float*)d_in[2];
    const int*   idx_kj = (const int*)d_in[3];
    const int*   idx_ji = (const int*)d_in[4];
    const float* W_rbf2 = (const float*)d_in[5];
    const float* b_rbf2 = (const float*)d_in[6];
    const float* W_sbf1 = (const float*)d_in[7];
    const float* W_sbf2 = (const float*)d_in[8];
    const float* W_kj   = (const float*)d_in[9];
    const float* b_kj   = (const float*)d_in[10];
    const float* W_down = (const float*)d_in[11];
    const float* b_down = (const float*)d_in[12];
    const float* W_up   = (const float*)d_in[13];
    const float* b_up   = (const float*)d_in[14];
    const float* W_r1a  = (const float*)d_in[15];
    const float* b_r1a  = (const float*)d_in[16];
    const float* W_r1b  = (const float*)d_in[17];
    const float* b_r1b  = (const float*)d_in[18];
    float* out = (float*)d_out;

    int E = in_sizes[0] / H;
    int T = in_sizes[3];

    cudaFuncSetAttribute(edge_kernel, cudaFuncAttributeMaxDynamicSharedMemorySize, SMEM_BYTES);
    cudaFuncSetAttribute(trip_kernel, cudaFuncAttributeMaxDynamicSharedMemorySize, SMEM_BYTES);
    cudaFuncSetAttribute(res_kernel, cudaFuncAttributeMaxDynamicSharedMemorySize, SMEM_BYTES);

    prep_kernel<<<480, 256>>>(W_kj, W_rbf2, W_down, W_sbf2, W_up, W_r1a, W_r1b, W_sbf1);
    zero_m_kernel<<<2048, 256>>>((size_t)E * H / 4);
    edge_kernel<<<(E + MT - 1) / MT, 256, SMEM_BYTES>>>(x, rbf, b_kj, b_rbf2, b_down, E);
    trip_kernel<<<(T + MT - 1) / MT, 256, SMEM_BYTES>>>(sbf, idx_kj, idx_ji, b_up, T);
    res_kernel<<<(E + MT - 1) / MT, 256, SMEM_BYTES>>>(x, b_r1a, b_r1b, out, E);
}